// round 2
// baseline (speedup 1.0000x reference)
#include <cuda_runtime.h>
#include <math.h>

static constexpr int Bsz = 512;
static constexpr int Tsz = 256;
static constexpr int NIN = 128;
static constexpr int NH  = 1024;
static constexpr int NH4 = 4096;

// Scratch (static device arrays: allowed; no runtime allocation)
__device__ float g_proj[(size_t)Tsz * Bsz * NH];   // 512 MB, time-major [T][B][H]
__device__ float g_h1[2][Bsz * NH];
__device__ float g_h2[2][Bsz * NH];
__device__ float g_c1[Bsz * NH];
__device__ float g_c2[Bsz * NH];

__device__ __forceinline__ float sigf(float v) { return 1.0f / (1.0f + __expf(-v)); }

// ---------------------------------------------------------------------------
// Zero initial states (runs at the start of every graph replay)
// ---------------------------------------------------------------------------
__global__ void zero_kernel() {
    int i = blockIdx.x * blockDim.x + threadIdx.x;
    if (i < Bsz * NH) {
        g_c1[i] = 0.f; g_c2[i] = 0.f;
        g_h1[0][i] = 0.f; g_h2[0][i] = 0.f;
    }
}

// ---------------------------------------------------------------------------
// proj[t][b][h] = relu(x[b][t][:] @ W[:, h] + bh[h])
// 128x128 tile, 256 threads, 8x8 per thread, K = 128 in chunks of 16.
// grid: (8 col tiles, 1024 row tiles). Row tile -> fixed t, 128 consecutive b.
// ---------------------------------------------------------------------------
__global__ __launch_bounds__(256) void proj_kernel(
    const float* __restrict__ x, const float* __restrict__ W,
    const float* __restrict__ bh)
{
    __shared__ float As[16][128];
    __shared__ float Bs[16][128];

    const int tid = threadIdx.x;
    const int tx = tid & 15, ty = tid >> 4;
    const int r0 = blockIdx.y * 128;
    const int t  = r0 >> 9;
    const int b0 = r0 & 511;
    const int h0 = blockIdx.x * 128;

    float acc[8][8];
#pragma unroll
    for (int i = 0; i < 8; i++)
#pragma unroll
        for (int j = 0; j < 8; j++) acc[i][j] = 0.f;

    for (int ck = 0; ck < NIN / 16; ck++) {
        const int k0 = ck * 16;
        // A tile: 128 rows x 16 k, transposed into As[k][row]
#pragma unroll
        for (int L = 0; L < 2; L++) {
            int id  = tid + L * 256;
            int row = id >> 2, quad = id & 3;
            float4 v = *(const float4*)(x + ((size_t)(b0 + row) * Tsz + t) * NIN + k0 + quad * 4);
            As[quad * 4 + 0][row] = v.x; As[quad * 4 + 1][row] = v.y;
            As[quad * 4 + 2][row] = v.z; As[quad * 4 + 3][row] = v.w;
        }
        // B tile: W rows k0..k0+15, cols h0..h0+127
#pragma unroll
        for (int L = 0; L < 2; L++) {
            int id = tid + L * 256;
            int kr = id >> 5, q = id & 31;
            *(float4*)&Bs[kr][q * 4] =
                *(const float4*)(W + (size_t)(k0 + kr) * NH + h0 + q * 4);
        }
        __syncthreads();
#pragma unroll
        for (int k = 0; k < 16; k++) {
            float a[8], bb[8];
            *(float4*)(a)     = *(const float4*)&As[k][ty * 8];
            *(float4*)(a + 4) = *(const float4*)&As[k][ty * 8 + 4];
            *(float4*)(bb)     = *(const float4*)&Bs[k][tx * 8];
            *(float4*)(bb + 4) = *(const float4*)&Bs[k][tx * 8 + 4];
#pragma unroll
            for (int i = 0; i < 8; i++)
#pragma unroll
                for (int j = 0; j < 8; j++) acc[i][j] = fmaf(a[i], bb[j], acc[i][j]);
        }
        __syncthreads();
    }

#pragma unroll
    for (int i = 0; i < 8; i++) {
        int b = b0 + ty * 8 + i;
        size_t base = ((size_t)t * Bsz + b) * NH + h0;
#pragma unroll
        for (int j = 0; j < 8; j++) {
            float v = acc[i][j] + bh[h0 + tx * 8 + j];
            g_proj[base + tx * 8 + j] = v > 0.f ? v : 0.f;
        }
    }
}

// ---------------------------------------------------------------------------
// One LSTM cell step:  z = [A0, A1] @ Wk + bias  (K = 2048),  gates fused.
// Column tiling: 32 units x 4 gates interleaved (eff_col = unit_local*4+gate)
// so each thread's 8 accumulator cols contain 2 full {i,j,f,o} gate sets.
// grid: (32 unit tiles, 4 row tiles), 256 threads, 8x8 per thread.
// ---------------------------------------------------------------------------
__global__ __launch_bounds__(256) void lstm_step_kernel(
    const float* __restrict__ A0, const float* __restrict__ A1,
    const float* __restrict__ Wk, const float* __restrict__ bias,
    float* __restrict__ cstate, float* __restrict__ hout)
{
    __shared__ float As[16][128];
    __shared__ float Bs[16][128];

    const int tid = threadIdx.x;
    const int tx = tid & 15, ty = tid >> 4;
    const int r0 = blockIdx.y * 128;   // batch rows
    const int u0 = blockIdx.x * 32;    // units

    float acc[8][8];
#pragma unroll
    for (int i = 0; i < 8; i++)
#pragma unroll
        for (int j = 0; j < 8; j++) acc[i][j] = 0.f;

    for (int ck = 0; ck < 128; ck++) {           // 128 chunks of 16 -> K=2048
        const float* Ap = (ck < 64) ? A0 : A1;
        const int k0 = (ck & 63) * 16;           // k within A0/A1
        const int kg = ck * 16;                  // global row in Wk

        // A tile (transposed)
#pragma unroll
        for (int L = 0; L < 2; L++) {
            int id  = tid + L * 256;
            int row = id >> 2, quad = id & 3;
            float4 v = *(const float4*)(Ap + (size_t)(r0 + row) * NH + k0 + quad * 4);
            As[quad * 4 + 0][row] = v.x; As[quad * 4 + 1][row] = v.y;
            As[quad * 4 + 2][row] = v.z; As[quad * 4 + 3][row] = v.w;
        }
        // B tile: gate-interleaved columns. id -> k(0..15), gate(0..3), uq(0..7)
#pragma unroll
        for (int L = 0; L < 2; L++) {
            int id = tid + L * 256;
            int k = id >> 5; int rem = id & 31; int g = rem >> 3; int uq = rem & 7;
            float4 v = *(const float4*)(Wk + (size_t)(kg + k) * NH4 + g * NH + u0 + uq * 4);
            Bs[k][(uq * 4 + 0) * 4 + g] = v.x;
            Bs[k][(uq * 4 + 1) * 4 + g] = v.y;
            Bs[k][(uq * 4 + 2) * 4 + g] = v.z;
            Bs[k][(uq * 4 + 3) * 4 + g] = v.w;
        }
        __syncthreads();
#pragma unroll
        for (int k = 0; k < 16; k++) {
            float a[8], bb[8];
            *(float4*)(a)     = *(const float4*)&As[k][ty * 8];
            *(float4*)(a + 4) = *(const float4*)&As[k][ty * 8 + 4];
            *(float4*)(bb)     = *(const float4*)&Bs[k][tx * 8];
            *(float4*)(bb + 4) = *(const float4*)&Bs[k][tx * 8 + 4];
#pragma unroll
            for (int i = 0; i < 8; i++)
#pragma unroll
                for (int j = 0; j < 8; j++) acc[i][j] = fmaf(a[i], bb[j], acc[i][j]);
        }
        __syncthreads();
    }

    // Fused gate epilogue: per thread row, 2 units each with {i,j,f,o}
#pragma unroll
    for (int i = 0; i < 8; i++) {
        int row = r0 + ty * 8 + i;
#pragma unroll
        for (int du = 0; du < 2; du++) {
            int ug = u0 + tx * 2 + du;
            float zi = acc[i][du * 4 + 0] + bias[ug];
            float zj = acc[i][du * 4 + 1] + bias[NH + ug];
            float zf = acc[i][du * 4 + 2] + bias[2 * NH + ug];
            float zo = acc[i][du * 4 + 3] + bias[3 * NH + ug];
            int idx = row * NH + ug;
            float cold = cstate[idx];
            float cn = cold * sigf(zf + 1.0f) + sigf(zi) * tanhf(zj);
            cstate[idx] = cn;
            hout[idx] = tanhf(cn) * sigf(zo);
        }
    }
}

// ---------------------------------------------------------------------------
extern "C" void kernel_launch(void* const* d_in, const int* in_sizes, int n_in,
                              void* d_out, int out_size)
{
    const float* x  = (const float*)d_in[0];
    const float* W  = (const float*)d_in[1];
    const float* bh = (const float*)d_in[2];
    const float* k1 = (const float*)d_in[3];
    const float* b1 = (const float*)d_in[4];
    const float* k2 = (const float*)d_in[5];
    const float* b2 = (const float*)d_in[6];
    float* out = (float*)d_out;

    float *proj, *h1, *h2, *c1, *c2;
    cudaGetSymbolAddress((void**)&proj, g_proj);
    cudaGetSymbolAddress((void**)&h1,   g_h1);
    cudaGetSymbolAddress((void**)&h2,   g_h2);
    cudaGetSymbolAddress((void**)&c1,   g_c1);
    cudaGetSymbolAddress((void**)&c2,   g_c2);

    zero_kernel<<<(Bsz * NH + 255) / 256, 256>>>();
    proj_kernel<<<dim3(8, (Tsz * Bsz) / 128), 256>>>(x, W, bh);

    for (int t = 0; t < Tsz; t++) {
        const int pin = t & 1, pout = 1 - pin;
        float* h1in  = h1 + (size_t)pin  * Bsz * NH;
        float* h1out = h1 + (size_t)pout * Bsz * NH;
        float* h2in  = h2 + (size_t)pin  * Bsz * NH;
        float* h2out = (t == Tsz - 1) ? out : h2 + (size_t)pout * Bsz * NH;

        lstm_step_kernel<<<dim3(32, 4), 256>>>(
            proj + (size_t)t * Bsz * NH, h1in, k1, b1, c1, h1out);
        lstm_step_kernel<<<dim3(32, 4), 256>>>(
            h1out, h2in, k2, b2, c2, h2out);
    }
}

// round 4
// speedup vs baseline: 3.3587x; 3.3587x over previous
#include <cuda_runtime.h>
#include <cuda_bf16.h>
#include <cstdint>
#include <math.h>

static constexpr int Bsz = 512;
static constexpr int Tsz = 256;
static constexpr int NIN = 128;
static constexpr int NH  = 1024;
static constexpr int NH4 = 4096;
static constexpr int TILE_ELEMS = 8192;    // 128 rows x 64 bf16 = 16KB

// ---------------- scratch (static device arrays) ----------------
// Pre-swizzled 16KB tile images, bf16 hi/lo planes.
__device__ __align__(16384) __nv_bfloat16 g_xsw [2][256][4][16][TILE_ELEMS]; // [hl][t][mt][kc]
__device__ __align__(16384) __nv_bfloat16 g_h1sw[2][2][4][16][TILE_ELEMS];   // [hl][buf][mt][kc]
__device__ __align__(16384) __nv_bfloat16 g_h2sw[2][2][4][16][TILE_ELEMS];
__device__ __align__(16384) __nv_bfloat16 g_w1sw[2][32][32][TILE_ELEMS];     // [hl][nt][kc]
__device__ __align__(16384) __nv_bfloat16 g_w2sw[2][32][32][TILE_ELEMS];
__device__ float g_c1[Bsz * NH];
__device__ float g_c2[Bsz * NH];

// ---------------- helpers ----------------
__device__ __forceinline__ float sigf(float v) { return 1.0f / (1.0f + __expf(-v)); }

__device__ __forceinline__ uint32_t s2u(const void* p) {
    uint32_t a;
    asm("{ .reg .u64 t; cvta.to.shared.u64 t, %1; cvt.u32.u64 %0, t; }" : "=r"(a) : "l"(p));
    return a;
}

#define MBAR_INIT(mb, cnt) \
    asm volatile("mbarrier.init.shared.b64 [%0], %1;" :: "r"(mb), "r"((uint32_t)(cnt)) : "memory")
#define MBAR_EXPECT(mb, bytes) \
    asm volatile("mbarrier.arrive.expect_tx.shared.b64 _, [%0], %1;" :: "r"(mb), "r"((uint32_t)(bytes)) : "memory")
#define MBAR_WAIT(mb, par) do { \
    uint32_t _m = (mb); uint32_t _p = (par); uint32_t _d; \
    asm volatile("{\n\t.reg .pred p;\n\t" \
        "mbarrier.try_wait.parity.acquire.cta.shared::cta.b64 p, [%1], %2;\n\t" \
        "selp.b32 %0, 1, 0, p;\n\t}" : "=r"(_d) : "r"(_m), "r"(_p) : "memory"); \
    if (!_d) { \
        asm volatile("{\n\t.reg .pred P1;\n\t" \
            "WL_%=:\n\t" \
            "mbarrier.try_wait.parity.acquire.cta.shared::cta.b64 P1, [%0], %1, 0x989680;\n\t" \
            "@P1 bra.uni WD_%=;\n\t" \
            "bra.uni WL_%=;\n\t" \
            "WD_%=:\n\t}" :: "r"(_m), "r"(_p) : "memory"); \
    } } while (0)

#define BULK_CP(dst, src, mb) \
    asm volatile("cp.async.bulk.shared::cluster.global.mbarrier::complete_tx::bytes [%0], [%1], %2, [%3];" \
        :: "r"((uint32_t)(dst)), "l"(src), "r"((uint32_t)16384), "r"((uint32_t)(mb)) : "memory")

#define LDSM4(r0, r1, r2, r3, a) \
    asm volatile("ldmatrix.sync.aligned.m8n8.x4.shared.b16 {%0,%1,%2,%3}, [%4];" \
        : "=r"(r0), "=r"(r1), "=r"(r2), "=r"(r3) : "r"(a))

#define MMA16816(c0, c1, c2, c3, a0, a1, a2, a3, b0, b1) \
    asm volatile("mma.sync.aligned.m16n8k16.row.col.f32.bf16.bf16.f32 " \
        "{%0,%1,%2,%3},{%4,%5,%6,%7},{%8,%9},{%0,%1,%2,%3};" \
        : "+f"(c0), "+f"(c1), "+f"(c2), "+f"(c3) \
        : "r"(a0), "r"(a1), "r"(a2), "r"(a3), "r"(b0), "r"(b1))

// ---------------------------------------------------------------------------
// Zero initial states (every replay)
// ---------------------------------------------------------------------------
__global__ void zero_kernel() {
    int i = blockIdx.x * blockDim.x + threadIdx.x;
    const int N = Bsz * NH;   // == one [mt][kc] image set (524288 elems)
    if (i < N) {
        g_c1[i] = 0.f; g_c2[i] = 0.f;
        __nv_bfloat16 z = __float2bfloat16(0.f);
        __nv_bfloat16* h1 = &g_h1sw[0][0][0][0][0];
        __nv_bfloat16* h2 = &g_h2sw[0][0][0][0][0];
        h1[i] = z; h1[2 * N + i] = z;   // hi buf0, lo buf0
        h2[i] = z; h2[2 * N + i] = z;
    }
}

// ---------------------------------------------------------------------------
// Weight conversion. Output layout: W'[n'][k], n' interleaved per 32-col group:
//   group = n'>>5, w = n'&31; half = w>>4 (0: i/j, 1: f/o);
//   unit = group*8 + ((w&15)>>1); gate = half*2 + (w&1)  (0:i 1:j 2:f 3:o)
// Stored as bf16 hi/lo SW128-swizzled tiles [nt][kc][128 x 64].
// ---------------------------------------------------------------------------
__global__ void wconv_kernel(const float* __restrict__ src,
                             __nv_bfloat16* __restrict__ dHi,
                             __nv_bfloat16* __restrict__ dLo) {
    int id = blockIdx.x * blockDim.x + threadIdx.x;   // 4096 cols x 256 k-octets
    int n  = id & 4095;
    int k0 = (id >> 12) * 8;

    int grp = n >> 5, w = n & 31;
    int half = w >> 4, idx = w & 15;
    int unit = grp * 8 + (idx >> 1);
    int gsel = half * 2 + (idx & 1);
    int scol = gsel * NH + unit;

    int nt = n >> 7, rl = n & 127;
    int kc = k0 >> 6, kl0 = k0 & 63;

    union { __nv_bfloat16 b[8]; uint4 v; } ph, pl;
#pragma unroll
    for (int j = 0; j < 8; j++) {
        float wv = src[(size_t)(k0 + j) * NH4 + scol];
        __nv_bfloat16 h = __float2bfloat16(wv);
        ph.b[j] = h;
        pl.b[j] = __float2bfloat16(wv - __bfloat162float(h));
    }
    size_t ib = (size_t)(nt * 32 + kc) * TILE_ELEMS;
    uint32_t off = (uint32_t)(rl * 128) + (uint32_t)((kl0 * 2) ^ ((rl & 7) << 4));
    *(uint4*)((char*)(dHi + ib) + off) = ph.v;
    *(uint4*)((char*)(dLo + ib) + off) = pl.v;
}

// ---------------------------------------------------------------------------
// proj = relu(x @ W + b), written as bf16 hi/lo swizzled tile images
// ---------------------------------------------------------------------------
__global__ __launch_bounds__(256) void proj_kernel(
    const float* __restrict__ x, const float* __restrict__ W,
    const float* __restrict__ bh)
{
    __shared__ float As[16][128];
    __shared__ float Bs[16][128];

    const int tid = threadIdx.x;
    const int tx = tid & 15, ty = tid >> 4;
    const int r0 = blockIdx.y * 128;
    const int t  = r0 >> 9;
    const int b0 = r0 & 511;
    const int h0 = blockIdx.x * 128;

    float acc[8][8];
#pragma unroll
    for (int i = 0; i < 8; i++)
#pragma unroll
        for (int j = 0; j < 8; j++) acc[i][j] = 0.f;

    for (int ck = 0; ck < NIN / 16; ck++) {
        const int k0 = ck * 16;
#pragma unroll
        for (int L = 0; L < 2; L++) {
            int id  = tid + L * 256;
            int row = id >> 2, quad = id & 3;
            float4 v = *(const float4*)(x + ((size_t)(b0 + row) * Tsz + t) * NIN + k0 + quad * 4);
            As[quad * 4 + 0][row] = v.x; As[quad * 4 + 1][row] = v.y;
            As[quad * 4 + 2][row] = v.z; As[quad * 4 + 3][row] = v.w;
        }
#pragma unroll
        for (int L = 0; L < 2; L++) {
            int id = tid + L * 256;
            int kr = id >> 5, q = id & 31;
            *(float4*)&Bs[kr][q * 4] = *(const float4*)(W + (size_t)(k0 + kr) * NH + h0 + q * 4);
        }
        __syncthreads();
#pragma unroll
        for (int k = 0; k < 16; k++) {
            float a[8], bb[8];
            *(float4*)(a)      = *(const float4*)&As[k][ty * 8];
            *(float4*)(a + 4)  = *(const float4*)&As[k][ty * 8 + 4];
            *(float4*)(bb)     = *(const float4*)&Bs[k][tx * 8];
            *(float4*)(bb + 4) = *(const float4*)&Bs[k][tx * 8 + 4];
#pragma unroll
            for (int i = 0; i < 8; i++)
#pragma unroll
                for (int j = 0; j < 8; j++) acc[i][j] = fmaf(a[i], bb[j], acc[i][j]);
        }
        __syncthreads();
    }

    const int colbase = h0 + tx * 8;
    const int kc = colbase >> 6, kl0 = colbase & 63;
    __nv_bfloat16* xhi = &g_xsw[0][0][0][0][0];
    __nv_bfloat16* xlo = xhi + (size_t)256 * 4 * 16 * TILE_ELEMS;
#pragma unroll
    for (int i = 0; i < 8; i++) {
        int b = b0 + ty * 8 + i;
        int mtL = b >> 7, rl = b & 127;
        union { __nv_bfloat16 e[8]; uint4 v; } ph, pl;
#pragma unroll
        for (int j = 0; j < 8; j++) {
            float v = acc[i][j] + bh[colbase + j];
            v = v > 0.f ? v : 0.f;
            __nv_bfloat16 h = __float2bfloat16(v);
            ph.e[j] = h;
            pl.e[j] = __float2bfloat16(v - __bfloat162float(h));
        }
        size_t ib = ((size_t)(t * 4 + mtL) * 16 + kc) * TILE_ELEMS;
        uint32_t off = (uint32_t)(rl * 128) + (uint32_t)((kl0 * 2) ^ ((rl & 7) << 4));
        *(uint4*)((char*)(xhi + ib) + off) = ph.v;
        *(uint4*)((char*)(xlo + ib) + off) = pl.v;
    }
}

// ---------------------------------------------------------------------------
// LSTM cell step: Z = [Ax | Ah] @ W' (bf16 3-pass HMMA) + bias, fused gates.
// grid (nt=32, mt=4), 256 threads (8 warps: 2m x 4n), warp tile 64x32.
// SMEM: 2 stages x {Ahi, Alo, Bhi, Blo} x 16KB = 128KB + mbarriers.
// ---------------------------------------------------------------------------
__global__ __launch_bounds__(256, 1) void lstm_step_hmma(
    const __nv_bfloat16* __restrict__ AxHi, const __nv_bfloat16* __restrict__ AxLo,
    const __nv_bfloat16* __restrict__ AhHi, const __nv_bfloat16* __restrict__ AhLo,
    const __nv_bfloat16* __restrict__ WHi,  const __nv_bfloat16* __restrict__ WLo,
    const float* __restrict__ bias, float* __restrict__ cst,
    __nv_bfloat16* __restrict__ HoHi, __nv_bfloat16* __restrict__ HoLo,
    float* __restrict__ outp)
{
    extern __shared__ __align__(1024) char smem[];
    const int tid = threadIdx.x, lane = tid & 31, wid = tid >> 5;
    const int wm = wid >> 2, wn = wid & 3;       // 2 x 4 warps
    const int nt = blockIdx.x, mt = blockIdx.y;
    const uint32_t sb = s2u(smem);
    const uint32_t mb0 = sb + 131072, mb1 = sb + 131080;

    if (tid == 0) { MBAR_INIT(mb0, 1); MBAR_INIT(mb1, 1); }
    __syncthreads();

    // per-thread ldmatrix base offsets
    const int l15 = lane & 15;
    const uint32_t khalf = (uint32_t)((lane >> 4) << 4);   // 0 or 16 bytes
    const uint32_t xr = (uint32_t)((l15 & 7) << 4);        // swizzle xor pattern
    uint32_t baseA[4], baseB[2];
#pragma unroll
    for (int mi = 0; mi < 4; mi++) baseA[mi] = (uint32_t)((wm * 64 + mi * 16 + l15) * 128);
#pragma unroll
    for (int p = 0; p < 2; p++)    baseB[p]  = (uint32_t)((wn * 32 + p * 16 + l15) * 128);

    float acc[4][4][4];
#pragma unroll
    for (int mi = 0; mi < 4; mi++)
#pragma unroll
        for (int nf = 0; nf < 4; nf++)
#pragma unroll
            for (int c = 0; c < 4; c++) acc[mi][nf][c] = 0.f;

    auto issue = [&](int c) {
        int s = c & 1;
        uint32_t base = sb + (uint32_t)s * 65536;
        const __nv_bfloat16 *ah_, *al_;
        if (c < 16) {
            ah_ = AxHi + (size_t)(mt * 16 + c) * TILE_ELEMS;
            al_ = AxLo + (size_t)(mt * 16 + c) * TILE_ELEMS;
        } else {
            ah_ = AhHi + (size_t)(mt * 16 + c - 16) * TILE_ELEMS;
            al_ = AhLo + (size_t)(mt * 16 + c - 16) * TILE_ELEMS;
        }
        const __nv_bfloat16* bh_ = WHi + (size_t)(nt * 32 + c) * TILE_ELEMS;
        const __nv_bfloat16* bl_ = WLo + (size_t)(nt * 32 + c) * TILE_ELEMS;
        uint32_t mb = (s == 0) ? mb0 : mb1;
        MBAR_EXPECT(mb, 65536);
        BULK_CP(base,         ah_, mb);
        BULK_CP(base + 16384, al_, mb);
        BULK_CP(base + 32768, bh_, mb);
        BULK_CP(base + 49152, bl_, mb);
    };

    if (tid == 0) { issue(0); issue(1); }

    for (int c = 0; c < 32; c++) {
        const int s = c & 1;
        MBAR_WAIT((s == 0) ? mb0 : mb1, (c >> 1) & 1);
        const uint32_t stg  = sb + (uint32_t)s * 65536;
        const uint32_t aHiB = stg, aLoB = stg + 16384, bHiB = stg + 32768, bLoB = stg + 49152;

#pragma unroll
        for (int k16 = 0; k16 < 4; k16++) {
            const uint32_t kx = ((uint32_t)(k16 * 32) + khalf) ^ xr;

            uint32_t aH[4][4], bH[4][2];
#pragma unroll
            for (int mi = 0; mi < 4; mi++)
                LDSM4(aH[mi][0], aH[mi][1], aH[mi][2], aH[mi][3], aHiB + baseA[mi] + kx);
#pragma unroll
            for (int p = 0; p < 2; p++) {
                uint32_t q0, q1, q2, q3;
                LDSM4(q0, q1, q2, q3, bHiB + baseB[p] + kx);
                bH[2 * p][0] = q0; bH[2 * p][1] = q2;
                bH[2 * p + 1][0] = q1; bH[2 * p + 1][1] = q3;
            }
            // pass 1: Ahi * Bhi
#pragma unroll
            for (int mi = 0; mi < 4; mi++)
#pragma unroll
                for (int nf = 0; nf < 4; nf++)
                    MMA16816(acc[mi][nf][0], acc[mi][nf][1], acc[mi][nf][2], acc[mi][nf][3],
                             aH[mi][0], aH[mi][1], aH[mi][2], aH[mi][3], bH[nf][0], bH[nf][1]);
            // pass 2: Alo * Bhi
            {
                uint32_t aL[4][4];
#pragma unroll
                for (int mi = 0; mi < 4; mi++)
                    LDSM4(aL[mi][0], aL[mi][1], aL[mi][2], aL[mi][3], aLoB + baseA[mi] + kx);
#pragma unroll
                for (int mi = 0; mi < 4; mi++)
#pragma unroll
                    for (int nf = 0; nf < 4; nf++)
                        MMA16816(acc[mi][nf][0], acc[mi][nf][1], acc[mi][nf][2], acc[mi][nf][3],
                                 aL[mi][0], aL[mi][1], aL[mi][2], aL[mi][3], bH[nf][0], bH[nf][1]);
            }
            // pass 3: Ahi * Blo
            {
                uint32_t bL[4][2];
#pragma unroll
                for (int p = 0; p < 2; p++) {
                    uint32_t q0, q1, q2, q3;
                    LDSM4(q0, q1, q2, q3, bLoB + baseB[p] + kx);
                    bL[2 * p][0] = q0; bL[2 * p][1] = q2;
                    bL[2 * p + 1][0] = q1; bL[2 * p + 1][1] = q3;
                }
#pragma unroll
                for (int mi = 0; mi < 4; mi++)
#pragma unroll
                    for (int nf = 0; nf < 4; nf++)
                        MMA16816(acc[mi][nf][0], acc[mi][nf][1], acc[mi][nf][2], acc[mi][nf][3],
                                 aH[mi][0], aH[mi][1], aH[mi][2], aH[mi][3], bL[nf][0], bL[nf][1]);
            }
        }
        __syncthreads();
        if (tid == 0 && c + 2 < 32) issue(c + 2);
    }

    // ---------------- fused gate epilogue (register-local, no shuffles) ----
    const int q = lane & 3, g = lane >> 2;
    const int gbase = (nt * 4 + wn) * 8;
    float bi[2][4];
#pragma unroll
    for (int ue = 0; ue < 2; ue++) {
        int u = gbase + q + 4 * ue;
        bi[ue][0] = bias[u];
        bi[ue][1] = bias[NH + u];
        bi[ue][2] = bias[2 * NH + u] + 1.0f;   // FORGET_BIAS folded in
        bi[ue][3] = bias[3 * NH + u];
    }

#pragma unroll
    for (int mi = 0; mi < 4; mi++) {
#pragma unroll
        for (int d = 0; d < 2; d++) {
            const int rl = wm * 64 + mi * 16 + g + 8 * d;
            const int rg = mt * 128 + rl;
#pragma unroll
            for (int ue = 0; ue < 2; ue++) {
                const int u = gbase + q + 4 * ue;
                float zi = acc[mi][ue][2 * d + 0]     + bi[ue][0];
                float zj = acc[mi][ue][2 * d + 1]     + bi[ue][1];
                float zf = acc[mi][2 + ue][2 * d + 0] + bi[ue][2];
                float zo = acc[mi][2 + ue][2 * d + 1] + bi[ue][3];

                size_t ci = (size_t)rg * NH + u;
                float cn = cst[ci] * sigf(zf) + sigf(zi) * tanhf(zj);
                cst[ci] = cn;
                float hv = tanhf(cn) * sigf(zo);

                __nv_bfloat16 hh = __float2bfloat16(hv);
                __nv_bfloat16 hl = __float2bfloat16(hv - __bfloat162float(hh));
                int kc = u >> 6, kl = u & 63;
                size_t ib = (size_t)(mt * 16 + kc) * TILE_ELEMS;
                uint32_t off = (uint32_t)(rl * 128) + (uint32_t)((kl * 2) ^ ((rl & 7) << 4));
                *(__nv_bfloat16*)((char*)(HoHi + ib) + off) = hh;
                *(__nv_bfloat16*)((char*)(HoLo + ib) + off) = hl;

                if (outp) outp[ci] = hv;
            }
        }
    }
}

// ---------------------------------------------------------------------------
extern "C" void kernel_launch(void* const* d_in, const int* in_sizes, int n_in,
                              void* d_out, int out_size)
{
    const float* x  = (const float*)d_in[0];
    const float* W  = (const float*)d_in[1];
    const float* bh = (const float*)d_in[2];
    const float* k1 = (const float*)d_in[3];
    const float* b1 = (const float*)d_in[4];
    const float* k2 = (const float*)d_in[5];
    const float* b2 = (const float*)d_in[6];
    float* out = (float*)d_out;

    __nv_bfloat16 *xsw, *h1sw, *h2sw, *w1sw, *w2sw;
    float *c1, *c2;
    cudaGetSymbolAddress((void**)&xsw,  g_xsw);
    cudaGetSymbolAddress((void**)&h1sw, g_h1sw);
    cudaGetSymbolAddress((void**)&h2sw, g_h2sw);
    cudaGetSymbolAddress((void**)&w1sw, g_w1sw);
    cudaGetSymbolAddress((void**)&w2sw, g_w2sw);
    cudaGetSymbolAddress((void**)&c1,   g_c1);
    cudaGetSymbolAddress((void**)&c2,   g_c2);

    static bool attr_set = false;
    if (!attr_set) {
        cudaFuncSetAttribute(lstm_step_hmma,
                             cudaFuncAttributeMaxDynamicSharedMemorySize, 131136);
        attr_set = true;
    }

    const size_t IMG  = (size_t)4 * 16 * TILE_ELEMS;    // 524288 elems
    const size_t WIMG = (size_t)32 * 32 * TILE_ELEMS;

    zero_kernel<<<(Bsz * NH + 255) / 256, 256>>>();
    wconv_kernel<<<4096, 256>>>(k1, w1sw, w1sw + WIMG);
    wconv_kernel<<<4096, 256>>>(k2, w2sw, w2sw + WIMG);
    proj_kernel<<<dim3(8, (Tsz * Bsz) / 128), 256>>>(x, W, bh);

    for (int t = 0; t < Tsz; t++) {
        const int pin = t & 1, pout = 1 - pin;

        const __nv_bfloat16* AxHi = xsw + (size_t)t * IMG;
        const __nv_bfloat16* AxLo = xsw + (size_t)(256 + t) * IMG;

        __nv_bfloat16* h1hi_in  = h1sw + (size_t)pin * IMG;
        __nv_bfloat16* h1lo_in  = h1sw + (size_t)(2 + pin) * IMG;
        __nv_bfloat16* h1hi_out = h1sw + (size_t)pout * IMG;
        __nv_bfloat16* h1lo_out = h1sw + (size_t)(2 + pout) * IMG;

        __nv_bfloat16* h2hi_in  = h2sw + (size_t)pin * IMG;
        __nv_bfloat16* h2lo_in  = h2sw + (size_t)(2 + pin) * IMG;
        __nv_bfloat16* h2hi_out = h2sw + (size_t)pout * IMG;
        __nv_bfloat16* h2lo_out = h2sw + (size_t)(2 + pout) * IMG;

        lstm_step_hmma<<<dim3(32, 4), 256, 131136>>>(
            AxHi, AxLo, h1hi_in, h1lo_in,
            w1sw, w1sw + WIMG, b1, c1,
            h1hi_out, h1lo_out, nullptr);

        lstm_step_hmma<<<dim3(32, 4), 256, 131136>>>(
            h1hi_out, h1lo_out, h2hi_in, h2lo_in,
            w2sw, w2sw + WIMG, b2, c2,
            h2hi_out, h2lo_out, (t == Tsz - 1) ? out : nullptr);
    }
}

// round 6
// speedup vs baseline: 3.4026x; 1.0131x over previous
#include <cuda_runtime.h>
#include <cuda_bf16.h>
#include <cstdint>
#include <math.h>

static constexpr int Bsz = 512;
static constexpr int Tsz = 256;
static constexpr int NIN = 128;
static constexpr int NH  = 1024;
static constexpr int NH4 = 4096;
static constexpr int TILE_ELEMS = 8192;    // 128 rows x 64 bf16 = 16KB

// ---------------- scratch (static device arrays) ----------------
__device__ __align__(16384) __nv_bfloat16 g_xsw [2][256][4][16][TILE_ELEMS]; // [hl][t][mt][kc]
__device__ __align__(16384) __nv_bfloat16 g_h1sw[2][2][4][16][TILE_ELEMS];   // [hl][buf][mt][kc]
__device__ __align__(16384) __nv_bfloat16 g_h2sw[2][2][4][16][TILE_ELEMS];
__device__ __align__(16384) __nv_bfloat16 g_w1sw[2][32][32][TILE_ELEMS];     // [hl][nt][kc]
__device__ __align__(16384) __nv_bfloat16 g_w2sw[2][32][32][TILE_ELEMS];
__device__ float g_c1[Bsz * NH];
__device__ float g_c2[Bsz * NH];

// ---------------- helpers ----------------
__device__ __forceinline__ float sigf(float v) { return 1.0f / (1.0f + __expf(-v)); }

__device__ __forceinline__ uint32_t s2u(const void* p) {
    uint32_t a;
    asm("{ .reg .u64 t; cvta.to.shared.u64 t, %1; cvt.u32.u64 %0, t; }" : "=r"(a) : "l"(p));
    return a;
}

#define MBAR_INIT(mb, cnt) \
    asm volatile("mbarrier.init.shared.b64 [%0], %1;" :: "r"(mb), "r"((uint32_t)(cnt)) : "memory")
#define MBAR_EXPECT(mb, bytes) \
    asm volatile("mbarrier.arrive.expect_tx.shared.b64 _, [%0], %1;" :: "r"(mb), "r"((uint32_t)(bytes)) : "memory")
#define MBAR_ARRIVE(mb) \
    asm volatile("mbarrier.arrive.shared.b64 _, [%0];" :: "r"(mb) : "memory")
#define MBAR_WAIT(mb, par) do { \
    uint32_t _m = (mb); uint32_t _p = (par); uint32_t _d; \
    asm volatile("{\n\t.reg .pred p;\n\t" \
        "mbarrier.try_wait.parity.acquire.cta.shared::cta.b64 p, [%1], %2;\n\t" \
        "selp.b32 %0, 1, 0, p;\n\t}" : "=r"(_d) : "r"(_m), "r"(_p) : "memory"); \
    if (!_d) { \
        asm volatile("{\n\t.reg .pred P1;\n\t" \
            "WL_%=:\n\t" \
            "mbarrier.try_wait.parity.acquire.cta.shared::cta.b64 P1, [%0], %1, 0x989680;\n\t" \
            "@P1 bra.uni WD_%=;\n\t" \
            "bra.uni WL_%=;\n\t" \
            "WD_%=:\n\t}" :: "r"(_m), "r"(_p) : "memory"); \
    } } while (0)

#define BULK_CP(dst, src, mb) \
    asm volatile("cp.async.bulk.shared::cluster.global.mbarrier::complete_tx::bytes [%0], [%1], %2, [%3];" \
        :: "r"((uint32_t)(dst)), "l"(src), "r"((uint32_t)16384), "r"((uint32_t)(mb)) : "memory")

#define LDSM4(r0, r1, r2, r3, a) \
    asm volatile("ldmatrix.sync.aligned.m8n8.x4.shared.b16 {%0,%1,%2,%3}, [%4];" \
        : "=r"(r0), "=r"(r1), "=r"(r2), "=r"(r3) : "r"(a))

#define MMA16816(c0, c1, c2, c3, a0, a1, a2, a3, b0, b1) \
    asm volatile("mma.sync.aligned.m16n8k16.row.col.f32.bf16.bf16.f32 " \
        "{%0,%1,%2,%3},{%4,%5,%6,%7},{%8,%9},{%0,%1,%2,%3};" \
        : "+f"(c0), "+f"(c1), "+f"(c2), "+f"(c3) \
        : "r"(a0), "r"(a1), "r"(a2), "r"(a3), "r"(b0), "r"(b1))

// ---------------------------------------------------------------------------
__global__ void zero_kernel() {
    int i = blockIdx.x * blockDim.x + threadIdx.x;
    const int N = Bsz * NH;
    if (i < N) {
        g_c1[i] = 0.f; g_c2[i] = 0.f;
        __nv_bfloat16 z = __float2bfloat16(0.f);
        __nv_bfloat16* h1 = &g_h1sw[0][0][0][0][0];
        __nv_bfloat16* h2 = &g_h2sw[0][0][0][0][0];
        h1[i] = z; h1[2 * N + i] = z;
        h2[i] = z; h2[2 * N + i] = z;
    }
}

// ---------------------------------------------------------------------------
// Weight conversion (layout identical to R4 — numerically validated)
// ---------------------------------------------------------------------------
__global__ void wconv_kernel(const float* __restrict__ src,
                             __nv_bfloat16* __restrict__ dHi,
                             __nv_bfloat16* __restrict__ dLo) {
    int id = blockIdx.x * blockDim.x + threadIdx.x;
    int n  = id & 4095;
    int k0 = (id >> 12) * 8;

    int grp = n >> 5, w = n & 31;
    int half = w >> 4, idx = w & 15;
    int unit = grp * 8 + (idx >> 1);
    int gsel = half * 2 + (idx & 1);
    int scol = gsel * NH + unit;

    int nt = n >> 7, rl = n & 127;
    int kc = k0 >> 6, kl0 = k0 & 63;

    union { __nv_bfloat16 b[8]; uint4 v; } ph, pl;
#pragma unroll
    for (int j = 0; j < 8; j++) {
        float wv = src[(size_t)(k0 + j) * NH4 + scol];
        __nv_bfloat16 h = __float2bfloat16(wv);
        ph.b[j] = h;
        pl.b[j] = __float2bfloat16(wv - __bfloat162float(h));
    }
    size_t ib = (size_t)(nt * 32 + kc) * TILE_ELEMS;
    uint32_t off = (uint32_t)(rl * 128) + (uint32_t)((kl0 * 2) ^ ((rl & 7) << 4));
    *(uint4*)((char*)(dHi + ib) + off) = ph.v;
    *(uint4*)((char*)(dLo + ib) + off) = pl.v;
}

// ---------------------------------------------------------------------------
// proj = relu(x @ W + b) -> bf16 hi/lo swizzled tile images (identical to R4)
// ---------------------------------------------------------------------------
__global__ __launch_bounds__(256) void proj_kernel(
    const float* __restrict__ x, const float* __restrict__ W,
    const float* __restrict__ bh)
{
    __shared__ float As[16][128];
    __shared__ float Bs[16][128];

    const int tid = threadIdx.x;
    const int tx = tid & 15, ty = tid >> 4;
    const int r0 = blockIdx.y * 128;
    const int t  = r0 >> 9;
    const int b0 = r0 & 511;
    const int h0 = blockIdx.x * 128;

    float acc[8][8];
#pragma unroll
    for (int i = 0; i < 8; i++)
#pragma unroll
        for (int j = 0; j < 8; j++) acc[i][j] = 0.f;

    for (int ck = 0; ck < NIN / 16; ck++) {
        const int k0 = ck * 16;
#pragma unroll
        for (int L = 0; L < 2; L++) {
            int id  = tid + L * 256;
            int row = id >> 2, quad = id & 3;
            float4 v = *(const float4*)(x + ((size_t)(b0 + row) * Tsz + t) * NIN + k0 + quad * 4);
            As[quad * 4 + 0][row] = v.x; As[quad * 4 + 1][row] = v.y;
            As[quad * 4 + 2][row] = v.z; As[quad * 4 + 3][row] = v.w;
        }
#pragma unroll
        for (int L = 0; L < 2; L++) {
            int id = tid + L * 256;
            int kr = id >> 5, q = id & 31;
            *(float4*)&Bs[kr][q * 4] = *(const float4*)(W + (size_t)(k0 + kr) * NH + h0 + q * 4);
        }
        __syncthreads();
#pragma unroll
        for (int k = 0; k < 16; k++) {
            float a[8], bb[8];
            *(float4*)(a)      = *(const float4*)&As[k][ty * 8];
            *(float4*)(a + 4)  = *(const float4*)&As[k][ty * 8 + 4];
            *(float4*)(bb)     = *(const float4*)&Bs[k][tx * 8];
            *(float4*)(bb + 4) = *(const float4*)&Bs[k][tx * 8 + 4];
#pragma unroll
            for (int i = 0; i < 8; i++)
#pragma unroll
                for (int j = 0; j < 8; j++) acc[i][j] = fmaf(a[i], bb[j], acc[i][j]);
        }
        __syncthreads();
    }

    const int colbase = h0 + tx * 8;
    const int kc = colbase >> 6, kl0 = colbase & 63;
    __nv_bfloat16* xhi = &g_xsw[0][0][0][0][0];
    __nv_bfloat16* xlo = xhi + (size_t)256 * 4 * 16 * TILE_ELEMS;
#pragma unroll
    for (int i = 0; i < 8; i++) {
        int b = b0 + ty * 8 + i;
        int mtL = b >> 7, rl = b & 127;
        union { __nv_bfloat16 e[8]; uint4 v; } ph, pl;
#pragma unroll
        for (int j = 0; j < 8; j++) {
            float v = acc[i][j] + bh[colbase + j];
            v = v > 0.f ? v : 0.f;
            __nv_bfloat16 h = __float2bfloat16(v);
            ph.e[j] = h;
            pl.e[j] = __float2bfloat16(v - __bfloat162float(h));
        }
        size_t ib = ((size_t)(t * 4 + mtL) * 16 + kc) * TILE_ELEMS;
        uint32_t off = (uint32_t)(rl * 128) + (uint32_t)((kl0 * 2) ^ ((rl & 7) << 4));
        *(uint4*)((char*)(xhi + ib) + off) = ph.v;
        *(uint4*)((char*)(xlo + ib) + off) = pl.v;
    }
}

// ---------------------------------------------------------------------------
// LSTM cell step, warp-specialized 3-stage pipeline.
// 288 threads: warps 0-7 = consumers (2m x 4n, warp tile 64x32), warp 8 lane 0
// = producer (cp.async.bulk). SMEM: 3 stages x 64KB + mbarriers.
// ---------------------------------------------------------------------------
__global__ __launch_bounds__(288, 1) void lstm_step_hmma(
    const __nv_bfloat16* __restrict__ AxHi, const __nv_bfloat16* __restrict__ AxLo,
    const __nv_bfloat16* __restrict__ AhHi, const __nv_bfloat16* __restrict__ AhLo,
    const __nv_bfloat16* __restrict__ WHi,  const __nv_bfloat16* __restrict__ WLo,
    const float* __restrict__ bias, float* __restrict__ cst,
    __nv_bfloat16* __restrict__ HoHi, __nv_bfloat16* __restrict__ HoLo,
    float* __restrict__ outp)
{
    extern __shared__ __align__(1024) char smem[];
    const int tid = threadIdx.x, lane = tid & 31, wid = tid >> 5;
    const int nt = blockIdx.x, mt = blockIdx.y;
    const uint32_t sb = s2u(smem);
    const uint32_t mb_full = sb + 196608;       // 3 x 8B
    const uint32_t mb_cons = sb + 196632;       // 3 x 8B

    if (tid == 0) {
#pragma unroll
        for (int s = 0; s < 3; s++) {
            MBAR_INIT(mb_full + s * 8, 1);      // producer's expect_tx only
            MBAR_INIT(mb_cons + s * 8, 256);    // all consumer threads
        }
    }
    __syncthreads();

    // ---------------- producer ----------------
    if (tid == 256) {
        for (int c = 0; c < 32; c++) {
            const int s = c % 3, u = c / 3;
            if (c >= 3) MBAR_WAIT(mb_cons + s * 8, (u - 1) & 1);
            const uint32_t base = sb + (uint32_t)s * 65536;
            const __nv_bfloat16 *ah_, *al_;
            if (c < 16) {
                ah_ = AxHi + (size_t)(mt * 16 + c) * TILE_ELEMS;
                al_ = AxLo + (size_t)(mt * 16 + c) * TILE_ELEMS;
            } else {
                ah_ = AhHi + (size_t)(mt * 16 + c - 16) * TILE_ELEMS;
                al_ = AhLo + (size_t)(mt * 16 + c - 16) * TILE_ELEMS;
            }
            const __nv_bfloat16* bh_ = WHi + (size_t)(nt * 32 + c) * TILE_ELEMS;
            const __nv_bfloat16* bl_ = WLo + (size_t)(nt * 32 + c) * TILE_ELEMS;
            const uint32_t mb = mb_full + s * 8;
            MBAR_EXPECT(mb, 65536);
            BULK_CP(base,         ah_, mb);
            BULK_CP(base + 16384, al_, mb);
            BULK_CP(base + 32768, bh_, mb);
            BULK_CP(base + 49152, bl_, mb);
        }
        return;
    }
    if (wid >= 8) return;   // rest of warp 8 idles

    // ---------------- consumers ----------------
    const int wm = wid >> 2, wn = wid & 3;
    const int l15 = lane & 15;
    const uint32_t khalf = (uint32_t)((lane >> 4) << 4);
    const uint32_t xr = (uint32_t)((l15 & 7) << 4);
    uint32_t baseA[4], baseB[2];
#pragma unroll
    for (int mi = 0; mi < 4; mi++) baseA[mi] = (uint32_t)((wm * 64 + mi * 16 + l15) * 128);
#pragma unroll
    for (int p = 0; p < 2; p++)    baseB[p]  = (uint32_t)((wn * 32 + p * 16 + l15) * 128);

    float acc[4][4][4];
#pragma unroll
    for (int mi = 0; mi < 4; mi++)
#pragma unroll
        for (int nf = 0; nf < 4; nf++)
#pragma unroll
            for (int c = 0; c < 4; c++) acc[mi][nf][c] = 0.f;

    for (int c = 0; c < 32; c++) {
        const int s = c % 3, u = c / 3;
        MBAR_WAIT(mb_full + s * 8, u & 1);
        const uint32_t stg  = sb + (uint32_t)s * 65536;
        const uint32_t aHiB = stg, aLoB = stg + 16384, bHiB = stg + 32768, bLoB = stg + 49152;

#pragma unroll
        for (int k16 = 0; k16 < 4; k16++) {
            const uint32_t kx = ((uint32_t)(k16 * 32) + khalf) ^ xr;

            uint32_t aH[4][4], bH[4][2];
#pragma unroll
            for (int mi = 0; mi < 4; mi++)
                LDSM4(aH[mi][0], aH[mi][1], aH[mi][2], aH[mi][3], aHiB + baseA[mi] + kx);
#pragma unroll
            for (int p = 0; p < 2; p++) {
                uint32_t q0, q1, q2, q3;
                LDSM4(q0, q1, q2, q3, bHiB + baseB[p] + kx);
                bH[2 * p][0] = q0; bH[2 * p][1] = q2;
                bH[2 * p + 1][0] = q1; bH[2 * p + 1][1] = q3;
            }
#pragma unroll
            for (int mi = 0; mi < 4; mi++)
#pragma unroll
                for (int nf = 0; nf < 4; nf++)
                    MMA16816(acc[mi][nf][0], acc[mi][nf][1], acc[mi][nf][2], acc[mi][nf][3],
                             aH[mi][0], aH[mi][1], aH[mi][2], aH[mi][3], bH[nf][0], bH[nf][1]);
            {
                uint32_t aL[4][4];
#pragma unroll
                for (int mi = 0; mi < 4; mi++)
                    LDSM4(aL[mi][0], aL[mi][1], aL[mi][2], aL[mi][3], aLoB + baseA[mi] + kx);
#pragma unroll
                for (int mi = 0; mi < 4; mi++)
#pragma unroll
                    for (int nf = 0; nf < 4; nf++)
                        MMA16816(acc[mi][nf][0], acc[mi][nf][1], acc[mi][nf][2], acc[mi][nf][3],
                                 aL[mi][0], aL[mi][1], aL[mi][2], aL[mi][3], bH[nf][0], bH[nf][1]);
            }
            {
                uint32_t bL[4][2];
#pragma unroll
                for (int p = 0; p < 2; p++) {
                    uint32_t q0, q1, q2, q3;
                    LDSM4(q0, q1, q2, q3, bLoB + baseB[p] + kx);
                    bL[2 * p][0] = q0; bL[2 * p][1] = q2;
                    bL[2 * p + 1][0] = q1; bL[2 * p + 1][1] = q3;
                }
#pragma unroll
                for (int mi = 0; mi < 4; mi++)
#pragma unroll
                    for (int nf = 0; nf < 4; nf++)
                        MMA16816(acc[mi][nf][0], acc[mi][nf][1], acc[mi][nf][2], acc[mi][nf][3],
                                 aH[mi][0], aH[mi][1], aH[mi][2], aH[mi][3], bL[nf][0], bL[nf][1]);
            }
        }
        MBAR_ARRIVE(mb_cons + s * 8);
    }

    // ---------------- fused gate epilogue (identical math to R4) ----------
    const int q = lane & 3, g = lane >> 2;
    const int gbase = (nt * 4 + wn) * 8;
    float bi[2][4];
#pragma unroll
    for (int ue = 0; ue < 2; ue++) {
        int u = gbase + q + 4 * ue;
        bi[ue][0] = bias[u];
        bi[ue][1] = bias[NH + u];
        bi[ue][2] = bias[2 * NH + u] + 1.0f;
        bi[ue][3] = bias[3 * NH + u];
    }

#pragma unroll
    for (int mi = 0; mi < 4; mi++) {
#pragma unroll
        for (int d = 0; d < 2; d++) {
            const int rl = wm * 64 + mi * 16 + g + 8 * d;
            const int rg = mt * 128 + rl;
#pragma unroll
            for (int ue = 0; ue < 2; ue++) {
                const int u = gbase + q + 4 * ue;
                float zi = acc[mi][ue][2 * d + 0]     + bi[ue][0];
                float zj = acc[mi][ue][2 * d + 1]     + bi[ue][1];
                float zf = acc[mi][2 + ue][2 * d + 0] + bi[ue][2];
                float zo = acc[mi][2 + ue][2 * d + 1] + bi[ue][3];

                size_t ci = (size_t)rg * NH + u;
                float cn = cst[ci] * sigf(zf) + sigf(zi) * tanhf(zj);
                cst[ci] = cn;
                float hv = tanhf(cn) * sigf(zo);

                __nv_bfloat16 hh = __float2bfloat16(hv);
                __nv_bfloat16 hl = __float2bfloat16(hv - __bfloat162float(hh));
                int kc = u >> 6, kl = u & 63;
                size_t ib = (size_t)(mt * 16 + kc) * TILE_ELEMS;
                uint32_t off = (uint32_t)(rl * 128) + (uint32_t)((kl * 2) ^ ((rl & 7) << 4));
                *(__nv_bfloat16*)((char*)(HoHi + ib) + off) = hh;
                *(__nv_bfloat16*)((char*)(HoLo + ib) + off) = hl;

                if (outp) outp[ci] = hv;
            }
        }
    }
}

// ---------------------------------------------------------------------------
extern "C" void kernel_launch(void* const* d_in, const int* in_sizes, int n_in,
                              void* d_out, int out_size)
{
    const float* x  = (const float*)d_in[0];
    const float* W  = (const float*)d_in[1];
    const float* bh = (const float*)d_in[2];
    const float* k1 = (const float*)d_in[3];
    const float* b1 = (const float*)d_in[4];
    const float* k2 = (const float*)d_in[5];
    const float* b2 = (const float*)d_in[6];
    float* out = (float*)d_out;

    __nv_bfloat16 *xsw, *h1sw, *h2sw, *w1sw, *w2sw;
    float *c1, *c2;
    cudaGetSymbolAddress((void**)&xsw,  g_xsw);
    cudaGetSymbolAddress((void**)&h1sw, g_h1sw);
    cudaGetSymbolAddress((void**)&h2sw, g_h2sw);
    cudaGetSymbolAddress((void**)&w1sw, g_w1sw);
    cudaGetSymbolAddress((void**)&w2sw, g_w2sw);
    cudaGetSymbolAddress((void**)&c1,   g_c1);
    cudaGetSymbolAddress((void**)&c2,   g_c2);

    const int SMEM_BYTES = 196608 + 64;
    static bool attr_set = false;
    if (!attr_set) {
        cudaFuncSetAttribute(lstm_step_hmma,
                             cudaFuncAttributeMaxDynamicSharedMemorySize, SMEM_BYTES);
        attr_set = true;
    }

    const size_t IMG  = (size_t)4 * 16 * TILE_ELEMS;
    const size_t WIMG = (size_t)32 * 32 * TILE_ELEMS;

    zero_kernel<<<(Bsz * NH + 255) / 256, 256>>>();
    wconv_kernel<<<4096, 256>>>(k1, w1sw, w1sw + WIMG);
    wconv_kernel<<<4096, 256>>>(k2, w2sw, w2sw + WIMG);
    proj_kernel<<<dim3(8, (Tsz * Bsz) / 128), 256>>>(x, W, bh);

    for (int t = 0; t < Tsz; t++) {
        const int pin = t & 1, pout = 1 - pin;

        const __nv_bfloat16* AxHi = xsw + (size_t)t * IMG;
        const __nv_bfloat16* AxLo = xsw + (size_t)(256 + t) * IMG;

        __nv_bfloat16* h1hi_in  = h1sw + (size_t)pin * IMG;
        __nv_bfloat16* h1lo_in  = h1sw + (size_t)(2 + pin) * IMG;
        __nv_bfloat16* h1hi_out = h1sw + (size_t)pout * IMG;
        __nv_bfloat16* h1lo_out = h1sw + (size_t)(2 + pout) * IMG;

        __nv_bfloat16* h2hi_in  = h2sw + (size_t)pin * IMG;
        __nv_bfloat16* h2lo_in  = h2sw + (size_t)(2 + pin) * IMG;
        __nv_bfloat16* h2hi_out = h2sw + (size_t)pout * IMG;
        __nv_bfloat16* h2lo_out = h2sw + (size_t)(2 + pout) * IMG;

        lstm_step_hmma<<<dim3(32, 4), 288, SMEM_BYTES>>>(
            AxHi, AxLo, h1hi_in, h1lo_in,
            w1sw, w1sw + WIMG, b1, c1,
            h1hi_out, h1lo_out, nullptr);

        lstm_step_hmma<<<dim3(32, 4), 288, SMEM_BYTES>>>(
            h1hi_out, h1lo_out, h2hi_in, h2lo_in,
            w2sw, w2sw + WIMG, b2, c2,
            h2hi_out, h2lo_out, (t == Tsz - 1) ? out : nullptr);
    }
}

// round 8
// speedup vs baseline: 4.7493x; 1.3958x over previous
#include <cuda_runtime.h>
#include <cuda_fp16.h>
#include <cstdint>
#include <math.h>

static constexpr int Bsz = 512;
static constexpr int Tsz = 256;
static constexpr int NIN = 128;
static constexpr int NH  = 1024;
static constexpr int NH4 = 4096;
static constexpr int TILE_ELEMS = 8192;    // 128 rows x 64 fp16 = 16KB

// ---------------- scratch (static device arrays) ----------------
__device__ __align__(16384) __half g_xsw [256][4][16][TILE_ELEMS];  // [t][mt][kc]
__device__ __align__(16384) __half g_h1sw[2][4][16][TILE_ELEMS];    // [buf][mt][kc]
__device__ __align__(16384) __half g_h2sw[2][4][16][TILE_ELEMS];
__device__ __align__(16384) __half g_w1sw[2][32][32][TILE_ELEMS];   // [hi/lo][nt][kc]
__device__ __align__(16384) __half g_w2sw[2][32][32][TILE_ELEMS];
__device__ float g_c1[Bsz * NH];
__device__ float g_c2[Bsz * NH];

// ---------------- helpers ----------------
__device__ __forceinline__ float sigf(float v) { return 1.0f / (1.0f + __expf(-v)); }

__device__ __forceinline__ uint32_t s2u(const void* p) {
    uint32_t a;
    asm("{ .reg .u64 t; cvta.to.shared.u64 t, %1; cvt.u32.u64 %0, t; }" : "=r"(a) : "l"(p));
    return a;
}

#define MBAR_INIT(mb, cnt) \
    asm volatile("mbarrier.init.shared.b64 [%0], %1;" :: "r"(mb), "r"((uint32_t)(cnt)) : "memory")
#define MBAR_EXPECT(mb, bytes) \
    asm volatile("mbarrier.arrive.expect_tx.shared.b64 _, [%0], %1;" :: "r"(mb), "r"((uint32_t)(bytes)) : "memory")
#define MBAR_ARRIVE(mb) \
    asm volatile("mbarrier.arrive.shared.b64 _, [%0];" :: "r"(mb) : "memory")
#define MBAR_WAIT(mb, par) do { \
    uint32_t _m = (mb); uint32_t _p = (par); uint32_t _d; \
    asm volatile("{\n\t.reg .pred p;\n\t" \
        "mbarrier.try_wait.parity.acquire.cta.shared::cta.b64 p, [%1], %2;\n\t" \
        "selp.b32 %0, 1, 0, p;\n\t}" : "=r"(_d) : "r"(_m), "r"(_p) : "memory"); \
    if (!_d) { \
        asm volatile("{\n\t.reg .pred P1;\n\t" \
            "WL_%=:\n\t" \
            "mbarrier.try_wait.parity.acquire.cta.shared::cta.b64 P1, [%0], %1, 0x989680;\n\t" \
            "@P1 bra.uni WD_%=;\n\t" \
            "bra.uni WL_%=;\n\t" \
            "WD_%=:\n\t}" :: "r"(_m), "r"(_p) : "memory"); \
    } } while (0)

#define BULK_CP(dst, src, mb) \
    asm volatile("cp.async.bulk.shared::cluster.global.mbarrier::complete_tx::bytes [%0], [%1], %2, [%3];" \
        :: "r"((uint32_t)(dst)), "l"(src), "r"((uint32_t)16384), "r"((uint32_t)(mb)) : "memory")

#define LDSM4(r0, r1, r2, r3, a) \
    asm volatile("ldmatrix.sync.aligned.m8n8.x4.shared.b16 {%0,%1,%2,%3}, [%4];" \
        : "=r"(r0), "=r"(r1), "=r"(r2), "=r"(r3) : "r"(a))

#define MMA16816F(c0, c1, c2, c3, a0, a1, a2, a3, b0, b1) \
    asm volatile("mma.sync.aligned.m16n8k16.row.col.f32.f16.f16.f32 " \
        "{%0,%1,%2,%3},{%4,%5,%6,%7},{%8,%9},{%0,%1,%2,%3};" \
        : "+f"(c0), "+f"(c1), "+f"(c2), "+f"(c3) \
        : "r"(a0), "r"(a1), "r"(a2), "r"(a3), "r"(b0), "r"(b1))

// ---------------------------------------------------------------------------
__global__ void zero_kernel() {
    int i = blockIdx.x * blockDim.x + threadIdx.x;
    const int N = Bsz * NH;   // one [mt][kc] image (524288 halves)
    if (i < N) {
        g_c1[i] = 0.f; g_c2[i] = 0.f;
        __half z = __float2half(0.f);
        (&g_h1sw[0][0][0][0])[i] = z;
        (&g_h2sw[0][0][0][0])[i] = z;
    }
}

// ---------------------------------------------------------------------------
// Weight conversion: gate-interleaved fp16 hi/lo, swizzled tiles [nt][kc].
// Column interleave (validated in R4/R6): grp=n>>5, w=n&31; half=w>>4;
// unit=grp*8+((w&15)>>1); gate=half*2+(w&1)
// ---------------------------------------------------------------------------
__global__ void wconv_kernel(const float* __restrict__ src,
                             __half* __restrict__ dHi,
                             __half* __restrict__ dLo) {
    int id = blockIdx.x * blockDim.x + threadIdx.x;
    int n  = id & 4095;
    int k0 = (id >> 12) * 8;

    int grp = n >> 5, w = n & 31;
    int half_ = w >> 4, idx = w & 15;
    int unit = grp * 8 + (idx >> 1);
    int gsel = half_ * 2 + (idx & 1);
    int scol = gsel * NH + unit;

    int nt = n >> 7, rl = n & 127;
    int kc = k0 >> 6, kl0 = k0 & 63;

    union { __half b[8]; uint4 v; } ph, pl;
#pragma unroll
    for (int j = 0; j < 8; j++) {
        float wv = src[(size_t)(k0 + j) * NH4 + scol];
        __half h = __float2half_rn(wv);
        ph.b[j] = h;
        pl.b[j] = __float2half_rn(wv - __half2float(h));
    }
    size_t ib = (size_t)(nt * 32 + kc) * TILE_ELEMS;
    uint32_t off = (uint32_t)(rl * 128) + (uint32_t)((kl0 * 2) ^ ((rl & 7) << 4));
    *(uint4*)((char*)(dHi + ib) + off) = ph.v;
    *(uint4*)((char*)(dLo + ib) + off) = pl.v;
}

// ---------------------------------------------------------------------------
// proj = relu(x @ W + b) -> single fp16 plane, swizzled tile images
// ---------------------------------------------------------------------------
__global__ __launch_bounds__(256) void proj_kernel(
    const float* __restrict__ x, const float* __restrict__ W,
    const float* __restrict__ bh)
{
    __shared__ float As[16][128];
    __shared__ float Bs[16][128];

    const int tid = threadIdx.x;
    const int tx = tid & 15, ty = tid >> 4;
    const int r0 = blockIdx.y * 128;
    const int t  = r0 >> 9;
    const int b0 = r0 & 511;
    const int h0 = blockIdx.x * 128;

    float acc[8][8];
#pragma unroll
    for (int i = 0; i < 8; i++)
#pragma unroll
        for (int j = 0; j < 8; j++) acc[i][j] = 0.f;

    for (int ck = 0; ck < NIN / 16; ck++) {
        const int k0 = ck * 16;
#pragma unroll
        for (int L = 0; L < 2; L++) {
            int id  = tid + L * 256;
            int row = id >> 2, quad = id & 3;
            float4 v = *(const float4*)(x + ((size_t)(b0 + row) * Tsz + t) * NIN + k0 + quad * 4);
            As[quad * 4 + 0][row] = v.x; As[quad * 4 + 1][row] = v.y;
            As[quad * 4 + 2][row] = v.z; As[quad * 4 + 3][row] = v.w;
        }
#pragma unroll
        for (int L = 0; L < 2; L++) {
            int id = tid + L * 256;
            int kr = id >> 5, q = id & 31;
            *(float4*)&Bs[kr][q * 4] = *(const float4*)(W + (size_t)(k0 + kr) * NH + h0 + q * 4);
        }
        __syncthreads();
#pragma unroll
        for (int k = 0; k < 16; k++) {
            float a[8], bb[8];
            *(float4*)(a)      = *(const float4*)&As[k][ty * 8];
            *(float4*)(a + 4)  = *(const float4*)&As[k][ty * 8 + 4];
            *(float4*)(bb)     = *(const float4*)&Bs[k][tx * 8];
            *(float4*)(bb + 4) = *(const float4*)&Bs[k][tx * 8 + 4];
#pragma unroll
            for (int i = 0; i < 8; i++)
#pragma unroll
                for (int j = 0; j < 8; j++) acc[i][j] = fmaf(a[i], bb[j], acc[i][j]);
        }
        __syncthreads();
    }

    const int colbase = h0 + tx * 8;
    const int kc = colbase >> 6, kl0 = colbase & 63;
    __half* xsw = &g_xsw[0][0][0][0];
#pragma unroll
    for (int i = 0; i < 8; i++) {
        int b = b0 + ty * 8 + i;
        int mtL = b >> 7, rl = b & 127;
        union { __half e[8]; uint4 v; } ph;
#pragma unroll
        for (int j = 0; j < 8; j++) {
            float v = acc[i][j] + bh[colbase + j];
            v = v > 0.f ? v : 0.f;
            ph.e[j] = __float2half_rn(v);
        }
        size_t ib = ((size_t)(t * 4 + mtL) * 16 + kc) * TILE_ELEMS;
        uint32_t off = (uint32_t)(rl * 128) + (uint32_t)((kl0 * 2) ^ ((rl & 7) << 4));
        *(uint4*)((char*)(xsw + ib) + off) = ph.v;
    }
}

// ---------------------------------------------------------------------------
// LSTM cell step: z = [Ax | Ah] @ (Whi + Wlo), fp16 2-pass HMMA, fused gates.
// 288 threads: 8 consumer warps (2m x 4n, warp tile 64x32) + producer lane 256.
// SMEM: 4 stages x {A, Whi, Wlo} x 16KB = 192KB + mbarriers at +192KB.
// ---------------------------------------------------------------------------
__global__ __launch_bounds__(288, 1) void lstm_step_hmma(
    const __half* __restrict__ Ax, const __half* __restrict__ Ah,
    const __half* __restrict__ WHi, const __half* __restrict__ WLo,
    const float* __restrict__ bias, float* __restrict__ cst,
    __half* __restrict__ Ho, float* __restrict__ outp)
{
    extern __shared__ __align__(1024) char smem[];
    const int tid = threadIdx.x, lane = tid & 31, wid = tid >> 5;
    const int nt = blockIdx.x, mt = blockIdx.y;
    const uint32_t sb = s2u(smem);
    const uint32_t CTRL = 196608;
    const uint32_t mb_full = sb + CTRL;          // 4 x 8B
    const uint32_t mb_cons = sb + CTRL + 32;     // 4 x 8B

    if (tid == 0) {
#pragma unroll
        for (int s = 0; s < 4; s++) {
            MBAR_INIT(mb_full + s * 8, 1);
            MBAR_INIT(mb_cons + s * 8, 256);
        }
    }
    __syncthreads();

    // ---------------- producer ----------------
    if (tid == 256) {
        for (int c = 0; c < 32; c++) {
            const int s = c & 3, u = c >> 2;
            if (c >= 4) MBAR_WAIT(mb_cons + s * 8, (u - 1) & 1);
            const uint32_t base = sb + (uint32_t)s * 49152;
            const __half* a_ = (c < 16)
                ? Ax + (size_t)(mt * 16 + c) * TILE_ELEMS
                : Ah + (size_t)(mt * 16 + c - 16) * TILE_ELEMS;
            const __half* bh_ = WHi + (size_t)(nt * 32 + c) * TILE_ELEMS;
            const __half* bl_ = WLo + (size_t)(nt * 32 + c) * TILE_ELEMS;
            const uint32_t mb = mb_full + s * 8;
            MBAR_EXPECT(mb, 49152);
            BULK_CP(base,         a_,  mb);
            BULK_CP(base + 16384, bh_, mb);
            BULK_CP(base + 32768, bl_, mb);
        }
        return;
    }
    if (wid >= 8) return;

    // ---------------- consumers ----------------
    const int wm = wid >> 2, wn = wid & 3;
    const int l15 = lane & 15;
    const uint32_t khalf = (uint32_t)((lane >> 4) << 4);
    const uint32_t xr = (uint32_t)((l15 & 7) << 4);
    uint32_t baseA[4], baseB[2];
#pragma unroll
    for (int mi = 0; mi < 4; mi++) baseA[mi] = (uint32_t)((wm * 64 + mi * 16 + l15) * 128);
#pragma unroll
    for (int p = 0; p < 2; p++)    baseB[p]  = (uint32_t)((wn * 32 + p * 16 + l15) * 128);

    float acc[4][4][4];
#pragma unroll
    for (int mi = 0; mi < 4; mi++)
#pragma unroll
        for (int nf = 0; nf < 4; nf++)
#pragma unroll
            for (int c = 0; c < 4; c++) acc[mi][nf][c] = 0.f;

    for (int c = 0; c < 32; c++) {
        const int s = c & 3, u = c >> 2;
        MBAR_WAIT(mb_full + s * 8, u & 1);
        const uint32_t stg = sb + (uint32_t)s * 49152;
        const uint32_t aB = stg, wHiB = stg + 16384, wLoB = stg + 32768;

#pragma unroll
        for (int k16 = 0; k16 < 4; k16++) {
            const uint32_t kx = ((uint32_t)(k16 * 32) + khalf) ^ xr;

            uint32_t a[4][4], bH[4][2];
#pragma unroll
            for (int mi = 0; mi < 4; mi++)
                LDSM4(a[mi][0], a[mi][1], a[mi][2], a[mi][3], aB + baseA[mi] + kx);
#pragma unroll
            for (int p = 0; p < 2; p++) {
                uint32_t q0, q1, q2, q3;
                LDSM4(q0, q1, q2, q3, wHiB + baseB[p] + kx);
                bH[2 * p][0] = q0; bH[2 * p][1] = q2;
                bH[2 * p + 1][0] = q1; bH[2 * p + 1][1] = q3;
            }
#pragma unroll
            for (int mi = 0; mi < 4; mi++)
#pragma unroll
                for (int nf = 0; nf < 4; nf++)
                    MMA16816F(acc[mi][nf][0], acc[mi][nf][1], acc[mi][nf][2], acc[mi][nf][3],
                              a[mi][0], a[mi][1], a[mi][2], a[mi][3], bH[nf][0], bH[nf][1]);
            {
                uint32_t bL[4][2];
#pragma unroll
                for (int p = 0; p < 2; p++) {
                    uint32_t q0, q1, q2, q3;
                    LDSM4(q0, q1, q2, q3, wLoB + baseB[p] + kx);
                    bL[2 * p][0] = q0; bL[2 * p][1] = q2;
                    bL[2 * p + 1][0] = q1; bL[2 * p + 1][1] = q3;
                }
#pragma unroll
                for (int mi = 0; mi < 4; mi++)
#pragma unroll
                    for (int nf = 0; nf < 4; nf++)
                        MMA16816F(acc[mi][nf][0], acc[mi][nf][1], acc[mi][nf][2], acc[mi][nf][3],
                                  a[mi][0], a[mi][1], a[mi][2], a[mi][3], bL[nf][0], bL[nf][1]);
            }
        }
        MBAR_ARRIVE(mb_cons + s * 8);
    }

    // ---------------- fused gate epilogue ----------------
    const int q = lane & 3, g = lane >> 2;
    const int gbase = (nt * 4 + wn) * 8;
    float bi[2][4];
#pragma unroll
    for (int ue = 0; ue < 2; ue++) {
        int u = gbase + q + 4 * ue;
        bi[ue][0] = bias[u];
        bi[ue][1] = bias[NH + u];
        bi[ue][2] = bias[2 * NH + u] + 1.0f;     // FORGET_BIAS folded in
        bi[ue][3] = bias[3 * NH + u];
    }

#pragma unroll
    for (int mi = 0; mi < 4; mi++) {
#pragma unroll
        for (int d = 0; d < 2; d++) {
            const int rl = wm * 64 + mi * 16 + g + 8 * d;
            const int rg = mt * 128 + rl;
#pragma unroll
            for (int ue = 0; ue < 2; ue++) {
                const int u = gbase + q + 4 * ue;
                float zi = acc[mi][ue][2 * d + 0]     + bi[ue][0];
                float zj = acc[mi][ue][2 * d + 1]     + bi[ue][1];
                float zf = acc[mi][2 + ue][2 * d + 0] + bi[ue][2];
                float zo = acc[mi][2 + ue][2 * d + 1] + bi[ue][3];

                size_t ci = (size_t)rg * NH + u;
                float cn = cst[ci] * sigf(zf) + sigf(zi) * tanhf(zj);
                cst[ci] = cn;
                float hv = tanhf(cn) * sigf(zo);

                int kc = u >> 6, kl = u & 63;
                size_t ib = (size_t)(mt * 16 + kc) * TILE_ELEMS;
                uint32_t off = (uint32_t)(rl * 128) + (uint32_t)((kl * 2) ^ ((rl & 7) << 4));
                *(__half*)((char*)(Ho + ib) + off) = __float2half_rn(hv);

                if (outp) outp[ci] = hv;
            }
        }
    }
}

// ---------------------------------------------------------------------------
extern "C" void kernel_launch(void* const* d_in, const int* in_sizes, int n_in,
                              void* d_out, int out_size)
{
    const float* x  = (const float*)d_in[0];
    const float* W  = (const float*)d_in[1];
    const float* bh = (const float*)d_in[2];
    const float* k1 = (const float*)d_in[3];
    const float* b1 = (const float*)d_in[4];
    const float* k2 = (const float*)d_in[5];
    const float* b2 = (const float*)d_in[6];
    float* out = (float*)d_out;

    __half *xsw, *h1sw, *h2sw, *w1sw, *w2sw;
    float *c1, *c2;
    cudaGetSymbolAddress((void**)&xsw,  g_xsw);
    cudaGetSymbolAddress((void**)&h1sw, g_h1sw);
    cudaGetSymbolAddress((void**)&h2sw, g_h2sw);
    cudaGetSymbolAddress((void**)&w1sw, g_w1sw);
    cudaGetSymbolAddress((void**)&w2sw, g_w2sw);
    cudaGetSymbolAddress((void**)&c1,   g_c1);
    cudaGetSymbolAddress((void**)&c2,   g_c2);

    const int SMEM_BYTES = 196608 + 64;
    static bool attr_set = false;
    if (!attr_set) {
        cudaFuncSetAttribute(lstm_step_hmma,
                             cudaFuncAttributeMaxDynamicSharedMemorySize, SMEM_BYTES);
        attr_set = true;
    }

    const size_t IMG  = (size_t)4 * 16 * TILE_ELEMS;    // 524288 halves
    const size_t WIMG = (size_t)32 * 32 * TILE_ELEMS;

    zero_kernel<<<(Bsz * NH + 255) / 256, 256>>>();
    wconv_kernel<<<4096, 256>>>(k1, w1sw, w1sw + WIMG);
    wconv_kernel<<<4096, 256>>>(k2, w2sw, w2sw + WIMG);
    proj_kernel<<<dim3(8, (Tsz * Bsz) / 128), 256>>>(x, W, bh);

    for (int t = 0; t < Tsz; t++) {
        const int pin = t & 1, pout = 1 - pin;

        const __half* Axt = xsw + (size_t)t * IMG;
        __half* h1in  = h1sw + (size_t)pin  * IMG;
        __half* h1out = h1sw + (size_t)pout * IMG;
        __half* h2in  = h2sw + (size_t)pin  * IMG;
        __half* h2out = h2sw + (size_t)pout * IMG;

        lstm_step_hmma<<<dim3(32, 4), 288, SMEM_BYTES>>>(
            Axt, h1in, w1sw, w1sw + WIMG, b1, c1, h1out, nullptr);

        lstm_step_hmma<<<dim3(32, 4), 288, SMEM_BYTES>>>(
            h1out, h2in, w2sw, w2sw + WIMG, b2, c2, h2out,
            (t == Tsz - 1) ? out : nullptr);
    }
}

// round 9
// speedup vs baseline: 7.9113x; 1.6658x over previous
#include <cuda_runtime.h>
#include <cuda_fp16.h>
#include <cstdint>
#include <math.h>

static constexpr int Bsz = 512;
static constexpr int Tsz = 256;
static constexpr int NIN = 128;
static constexpr int NH  = 1024;
static constexpr int NH4 = 4096;
static constexpr int TILE_ELEMS = 8192;    // 128 rows x 64 fp16 = 16KB

// ---------------- scratch (static device arrays) ----------------
__device__ __align__(16384) __half g_xsw [256][4][16][TILE_ELEMS];  // [t][mt][kc]
__device__ __align__(16384) __half g_h1sw[2][4][16][TILE_ELEMS];    // [buf][mt][kc]
__device__ __align__(16384) __half g_h2sw[2][4][16][TILE_ELEMS];
__device__ __align__(16384) __half g_w1sw[32][32][TILE_ELEMS];      // [nt][kc]
__device__ __align__(16384) __half g_w2sw[32][32][TILE_ELEMS];
__device__ float g_c1[Bsz * NH];
__device__ float g_c2[Bsz * NH];

// ---------------- helpers ----------------
__device__ __forceinline__ float sigf(float v) { return 1.0f / (1.0f + __expf(-v)); }

__device__ __forceinline__ uint32_t s2u(const void* p) {
    uint32_t a;
    asm("{ .reg .u64 t; cvta.to.shared.u64 t, %1; cvt.u32.u64 %0, t; }" : "=r"(a) : "l"(p));
    return a;
}

#define MBAR_INIT(mb, cnt) \
    asm volatile("mbarrier.init.shared.b64 [%0], %1;" :: "r"(mb), "r"((uint32_t)(cnt)) : "memory")
#define MBAR_EXPECT(mb, bytes) \
    asm volatile("mbarrier.arrive.expect_tx.shared.b64 _, [%0], %1;" :: "r"(mb), "r"((uint32_t)(bytes)) : "memory")
#define MBAR_ARRIVE(mb) \
    asm volatile("mbarrier.arrive.shared.b64 _, [%0];" :: "r"(mb) : "memory")
#define MBAR_WAIT(mb, par) do { \
    uint32_t _m = (mb); uint32_t _p = (par); uint32_t _d; \
    asm volatile("{\n\t.reg .pred p;\n\t" \
        "mbarrier.try_wait.parity.acquire.cta.shared::cta.b64 p, [%1], %2;\n\t" \
        "selp.b32 %0, 1, 0, p;\n\t}" : "=r"(_d) : "r"(_m), "r"(_p) : "memory"); \
    if (!_d) { \
        asm volatile("{\n\t.reg .pred P1;\n\t" \
            "WL_%=:\n\t" \
            "mbarrier.try_wait.parity.acquire.cta.shared::cta.b64 P1, [%0], %1, 0x989680;\n\t" \
            "@P1 bra.uni WD_%=;\n\t" \
            "bra.uni WL_%=;\n\t" \
            "WD_%=:\n\t}" :: "r"(_m), "r"(_p) : "memory"); \
    } } while (0)

#define BULK_CP(dst, src, mb) \
    asm volatile("cp.async.bulk.shared::cluster.global.mbarrier::complete_tx::bytes [%0], [%1], %2, [%3];" \
        :: "r"((uint32_t)(dst)), "l"(src), "r"((uint32_t)16384), "r"((uint32_t)(mb)) : "memory")

#define LDSM4(r0, r1, r2, r3, a) \
    asm volatile("ldmatrix.sync.aligned.m8n8.x4.shared.b16 {%0,%1,%2,%3}, [%4];" \
        : "=r"(r0), "=r"(r1), "=r"(r2), "=r"(r3) : "r"(a))

#define MMA16816F(c0, c1, c2, c3, a0, a1, a2, a3, b0, b1) \
    asm volatile("mma.sync.aligned.m16n8k16.row.col.f32.f16.f16.f32 " \
        "{%0,%1,%2,%3},{%4,%5,%6,%7},{%8,%9},{%0,%1,%2,%3};" \
        : "+f"(c0), "+f"(c1), "+f"(c2), "+f"(c3) \
        : "r"(a0), "r"(a1), "r"(a2), "r"(a3), "r"(b0), "r"(b1))

// ---------------------------------------------------------------------------
__global__ void zero_kernel() {
    int i = blockIdx.x * blockDim.x + threadIdx.x;
    const int N = Bsz * NH;   // one [mt][kc] image (524288 halves)
    if (i < N) {
        g_c1[i] = 0.f; g_c2[i] = 0.f;
        __half z = __float2half(0.f);
        (&g_h1sw[0][0][0][0])[i] = z;
        (&g_h2sw[0][0][0][0])[i] = z;
    }
}

// ---------------------------------------------------------------------------
// Weight conversion: gate-interleaved single fp16 plane, swizzled tiles.
// Column interleave (validated R4/R6/R8): grp=n>>5, w=n&31; half=w>>4;
// unit=grp*8+((w&15)>>1); gate=half*2+(w&1)
// ---------------------------------------------------------------------------
__global__ void wconv_kernel(const float* __restrict__ src,
                             __half* __restrict__ dst) {
    int id = blockIdx.x * blockDim.x + threadIdx.x;
    int n  = id & 4095;
    int k0 = (id >> 12) * 8;

    int grp = n >> 5, w = n & 31;
    int half_ = w >> 4, idx = w & 15;
    int unit = grp * 8 + (idx >> 1);
    int gsel = half_ * 2 + (idx & 1);
    int scol = gsel * NH + unit;

    int nt = n >> 7, rl = n & 127;
    int kc = k0 >> 6, kl0 = k0 & 63;

    union { __half b[8]; uint4 v; } ph;
#pragma unroll
    for (int j = 0; j < 8; j++)
        ph.b[j] = __float2half_rn(src[(size_t)(k0 + j) * NH4 + scol]);

    size_t ib = (size_t)(nt * 32 + kc) * TILE_ELEMS;
    uint32_t off = (uint32_t)(rl * 128) + (uint32_t)((kl0 * 2) ^ ((rl & 7) << 4));
    *(uint4*)((char*)(dst + ib) + off) = ph.v;
}

// ---------------------------------------------------------------------------
// proj = relu(x @ W + b) -> single fp16 plane, swizzled tile images
// ---------------------------------------------------------------------------
__global__ __launch_bounds__(256) void proj_kernel(
    const float* __restrict__ x, const float* __restrict__ W,
    const float* __restrict__ bh)
{
    __shared__ float As[16][128];
    __shared__ float Bs[16][128];

    const int tid = threadIdx.x;
    const int tx = tid & 15, ty = tid >> 4;
    const int r0 = blockIdx.y * 128;
    const int t  = r0 >> 9;
    const int b0 = r0 & 511;
    const int h0 = blockIdx.x * 128;

    float acc[8][8];
#pragma unroll
    for (int i = 0; i < 8; i++)
#pragma unroll
        for (int j = 0; j < 8; j++) acc[i][j] = 0.f;

    for (int ck = 0; ck < NIN / 16; ck++) {
        const int k0 = ck * 16;
#pragma unroll
        for (int L = 0; L < 2; L++) {
            int id  = tid + L * 256;
            int row = id >> 2, quad = id & 3;
            float4 v = *(const float4*)(x + ((size_t)(b0 + row) * Tsz + t) * NIN + k0 + quad * 4);
            As[quad * 4 + 0][row] = v.x; As[quad * 4 + 1][row] = v.y;
            As[quad * 4 + 2][row] = v.z; As[quad * 4 + 3][row] = v.w;
        }
#pragma unroll
        for (int L = 0; L < 2; L++) {
            int id = tid + L * 256;
            int kr = id >> 5, q = id & 31;
            *(float4*)&Bs[kr][q * 4] = *(const float4*)(W + (size_t)(k0 + kr) * NH + h0 + q * 4);
        }
        __syncthreads();
#pragma unroll
        for (int k = 0; k < 16; k++) {
            float a[8], bb[8];
            *(float4*)(a)      = *(const float4*)&As[k][ty * 8];
            *(float4*)(a + 4)  = *(const float4*)&As[k][ty * 8 + 4];
            *(float4*)(bb)     = *(const float4*)&Bs[k][tx * 8];
            *(float4*)(bb + 4) = *(const float4*)&Bs[k][tx * 8 + 4];
#pragma unroll
            for (int i = 0; i < 8; i++)
#pragma unroll
                for (int j = 0; j < 8; j++) acc[i][j] = fmaf(a[i], bb[j], acc[i][j]);
        }
        __syncthreads();
    }

    const int colbase = h0 + tx * 8;
    const int kc = colbase >> 6, kl0 = colbase & 63;
    __half* xsw = &g_xsw[0][0][0][0];
#pragma unroll
    for (int i = 0; i < 8; i++) {
        int b = b0 + ty * 8 + i;
        int mtL = b >> 7, rl = b & 127;
        union { __half e[8]; uint4 v; } ph;
#pragma unroll
        for (int j = 0; j < 8; j++) {
            float v = acc[i][j] + bh[colbase + j];
            v = v > 0.f ? v : 0.f;
            ph.e[j] = __float2half_rn(v);
        }
        size_t ib = ((size_t)(t * 4 + mtL) * 16 + kc) * TILE_ELEMS;
        uint32_t off = (uint32_t)(rl * 128) + (uint32_t)((kl0 * 2) ^ ((rl & 7) << 4));
        *(uint4*)((char*)(xsw + ib) + off) = ph.v;
    }
}

// ---------------------------------------------------------------------------
// LSTM cell step: z = [Ax | Ah] @ W, single-pass fp16 HMMA, fused gates.
// 288 threads: 8 consumer warps (2m x 4n, warp tile 64x32) + producer lane 256.
// SMEM: 6 stages x {A, W} x 16KB = 192KB + mbarriers at +192KB.
// ---------------------------------------------------------------------------
__global__ __launch_bounds__(288, 1) void lstm_step_hmma(
    const __half* __restrict__ Ax, const __half* __restrict__ Ah,
    const __half* __restrict__ Wk,
    const float* __restrict__ bias, float* __restrict__ cst,
    __half* __restrict__ Ho, float* __restrict__ outp)
{
    extern __shared__ __align__(1024) char smem[];
    const int tid = threadIdx.x, lane = tid & 31, wid = tid >> 5;
    const int nt = blockIdx.x, mt = blockIdx.y;
    const uint32_t sb = s2u(smem);
    const uint32_t CTRL = 196608;
    const uint32_t mb_full = sb + CTRL;          // 6 x 8B
    const uint32_t mb_cons = sb + CTRL + 48;     // 6 x 8B

    if (tid == 0) {
#pragma unroll
        for (int s = 0; s < 6; s++) {
            MBAR_INIT(mb_full + s * 8, 1);
            MBAR_INIT(mb_cons + s * 8, 256);
        }
    }
    __syncthreads();

    // ---------------- producer ----------------
    if (tid == 256) {
        for (int c = 0; c < 32; c++) {
            const int s = c % 6, u = c / 6;
            if (c >= 6) MBAR_WAIT(mb_cons + s * 8, (u - 1) & 1);
            const uint32_t base = sb + (uint32_t)s * 32768;
            const __half* a_ = (c < 16)
                ? Ax + (size_t)(mt * 16 + c) * TILE_ELEMS
                : Ah + (size_t)(mt * 16 + c - 16) * TILE_ELEMS;
            const __half* w_ = Wk + (size_t)(nt * 32 + c) * TILE_ELEMS;
            const uint32_t mb = mb_full + s * 8;
            MBAR_EXPECT(mb, 32768);
            BULK_CP(base,         a_, mb);
            BULK_CP(base + 16384, w_, mb);
        }
        return;
    }
    if (wid >= 8) return;

    // ---------------- consumers ----------------
    const int wm = wid >> 2, wn = wid & 3;
    const int l15 = lane & 15;
    const uint32_t khalf = (uint32_t)((lane >> 4) << 4);
    const uint32_t xr = (uint32_t)((l15 & 7) << 4);
    uint32_t baseA[4], baseB[2];
#pragma unroll
    for (int mi = 0; mi < 4; mi++) baseA[mi] = (uint32_t)((wm * 64 + mi * 16 + l15) * 128);
#pragma unroll
    for (int p = 0; p < 2; p++)    baseB[p]  = (uint32_t)((wn * 32 + p * 16 + l15) * 128);

    float acc[4][4][4];
#pragma unroll
    for (int mi = 0; mi < 4; mi++)
#pragma unroll
        for (int nf = 0; nf < 4; nf++)
#pragma unroll
            for (int c = 0; c < 4; c++) acc[mi][nf][c] = 0.f;

    for (int c = 0; c < 32; c++) {
        const int s = c % 6, u = c / 6;
        MBAR_WAIT(mb_full + s * 8, u & 1);
        const uint32_t stg = sb + (uint32_t)s * 32768;
        const uint32_t aB = stg, wB = stg + 16384;

#pragma unroll
        for (int k16 = 0; k16 < 4; k16++) {
            const uint32_t kx = ((uint32_t)(k16 * 32) + khalf) ^ xr;

            uint32_t a[4][4], bH[4][2];
#pragma unroll
            for (int mi = 0; mi < 4; mi++)
                LDSM4(a[mi][0], a[mi][1], a[mi][2], a[mi][3], aB + baseA[mi] + kx);
#pragma unroll
            for (int p = 0; p < 2; p++) {
                uint32_t q0, q1, q2, q3;
                LDSM4(q0, q1, q2, q3, wB + baseB[p] + kx);
                bH[2 * p][0] = q0; bH[2 * p][1] = q2;
                bH[2 * p + 1][0] = q1; bH[2 * p + 1][1] = q3;
            }
#pragma unroll
            for (int mi = 0; mi < 4; mi++)
#pragma unroll
                for (int nf = 0; nf < 4; nf++)
                    MMA16816F(acc[mi][nf][0], acc[mi][nf][1], acc[mi][nf][2], acc[mi][nf][3],
                              a[mi][0], a[mi][1], a[mi][2], a[mi][3], bH[nf][0], bH[nf][1]);
        }
        MBAR_ARRIVE(mb_cons + s * 8);
    }

    // ---------------- fused gate epilogue ----------------
    const int q = lane & 3, g = lane >> 2;
    const int gbase = (nt * 4 + wn) * 8;
    float bi[2][4];
#pragma unroll
    for (int ue = 0; ue < 2; ue++) {
        int u = gbase + q + 4 * ue;
        bi[ue][0] = bias[u];
        bi[ue][1] = bias[NH + u];
        bi[ue][2] = bias[2 * NH + u] + 1.0f;     // FORGET_BIAS folded in
        bi[ue][3] = bias[3 * NH + u];
    }

#pragma unroll
    for (int mi = 0; mi < 4; mi++) {
#pragma unroll
        for (int d = 0; d < 2; d++) {
            const int rl = wm * 64 + mi * 16 + g + 8 * d;
            const int rg = mt * 128 + rl;
#pragma unroll
            for (int ue = 0; ue < 2; ue++) {
                const int u = gbase + q + 4 * ue;
                float zi = acc[mi][ue][2 * d + 0]     + bi[ue][0];
                float zj = acc[mi][ue][2 * d + 1]     + bi[ue][1];
                float zf = acc[mi][2 + ue][2 * d + 0] + bi[ue][2];
                float zo = acc[mi][2 + ue][2 * d + 1] + bi[ue][3];

                size_t ci = (size_t)rg * NH + u;
                float cn = cst[ci] * sigf(zf) + sigf(zi) * tanhf(zj);
                cst[ci] = cn;
                float hv = tanhf(cn) * sigf(zo);

                int kc = u >> 6, kl = u & 63;
                size_t ib = (size_t)(mt * 16 + kc) * TILE_ELEMS;
                uint32_t off = (uint32_t)(rl * 128) + (uint32_t)((kl * 2) ^ ((rl & 7) << 4));
                *(__half*)((char*)(Ho + ib) + off) = __float2half_rn(hv);

                if (outp) outp[ci] = hv;
            }
        }
    }
}

// ---------------------------------------------------------------------------
extern "C" void kernel_launch(void* const* d_in, const int* in_sizes, int n_in,
                              void* d_out, int out_size)
{
    const float* x  = (const float*)d_in[0];
    const float* W  = (const float*)d_in[1];
    const float* bh = (const float*)d_in[2];
    const float* k1 = (const float*)d_in[3];
    const float* b1 = (const float*)d_in[4];
    const float* k2 = (const float*)d_in[5];
    const float* b2 = (const float*)d_in[6];
    float* out = (float*)d_out;

    __half *xsw, *h1sw, *h2sw, *w1sw, *w2sw;
    float *c1, *c2;
    cudaGetSymbolAddress((void**)&xsw,  g_xsw);
    cudaGetSymbolAddress((void**)&h1sw, g_h1sw);
    cudaGetSymbolAddress((void**)&h2sw, g_h2sw);
    cudaGetSymbolAddress((void**)&w1sw, g_w1sw);
    cudaGetSymbolAddress((void**)&w2sw, g_w2sw);
    cudaGetSymbolAddress((void**)&c1,   g_c1);
    cudaGetSymbolAddress((void**)&c2,   g_c2);

    const int SMEM_BYTES = 196608 + 128;
    static bool attr_set = false;
    if (!attr_set) {
        cudaFuncSetAttribute(lstm_step_hmma,
                             cudaFuncAttributeMaxDynamicSharedMemorySize, SMEM_BYTES);
        attr_set = true;
    }

    const size_t IMG = (size_t)4 * 16 * TILE_ELEMS;    // 524288 halves

    zero_kernel<<<(Bsz * NH + 255) / 256, 256>>>();
    wconv_kernel<<<4096, 256>>>(k1, w1sw);
    wconv_kernel<<<4096, 256>>>(k2, w2sw);
    proj_kernel<<<dim3(8, (Tsz * Bsz) / 128), 256>>>(x, W, bh);

    for (int t = 0; t < Tsz; t++) {
        const int pin = t & 1, pout = 1 - pin;

        const __half* Axt = xsw + (size_t)t * IMG;
        __half* h1in  = h1sw + (size_t)pin  * IMG;
        __half* h1out = h1sw + (size_t)pout * IMG;
        __half* h2in  = h2sw + (size_t)pin  * IMG;
        __half* h2out = h2sw + (size_t)pout * IMG;

        lstm_step_hmma<<<dim3(32, 4), 288, SMEM_BYTES>>>(
            Axt, h1in, w1sw, b1, c1, h1out, nullptr);

        lstm_step_hmma<<<dim3(32, 4), 288, SMEM_BYTES>>>(
            h1out, h2in, w2sw, b2, c2, h2out,
            (t == Tsz - 1) ? out : nullptr);
    }
}

// round 10
// speedup vs baseline: 8.3914x; 1.0607x over previous
#include <cuda_runtime.h>
#include <cuda_fp16.h>
#include <cstdint>
#include <math.h>

static constexpr int Bsz = 512;
static constexpr int Tsz = 256;
static constexpr int NIN = 128;
static constexpr int NH  = 1024;
static constexpr int NH4 = 4096;
static constexpr int TILE_ELEMS = 8192;    // 128 rows x 64 fp16 = 16KB
static constexpr int NCTA = 128;           // persistent grid (<=148 SMs, 1 CTA/SM)

// ---------------- scratch (static device arrays) ----------------
__device__ __align__(16384) __half g_xsw [256][4][16][TILE_ELEMS];  // [t][mt][kc]
__device__ __align__(16384) __half g_h1sw[2][4][16][TILE_ELEMS];    // [buf][mt][kc]
__device__ __align__(16384) __half g_h2sw[2][4][16][TILE_ELEMS];
__device__ __align__(16384) __half g_w1sw[32][32][TILE_ELEMS];      // [nt][kc]
__device__ __align__(16384) __half g_w2sw[32][32][TILE_ELEMS];
__device__ float g_c1[Bsz * NH];
__device__ float g_c2[Bsz * NH];
__device__ unsigned g_bar;

// ---------------- helpers ----------------
__device__ __forceinline__ float sigf(float v) { return 1.0f / (1.0f + __expf(-v)); }

__device__ __forceinline__ uint32_t s2u(const void* p) {
    uint32_t a;
    asm("{ .reg .u64 t; cvta.to.shared.u64 t, %1; cvt.u32.u64 %0, t; }" : "=r"(a) : "l"(p));
    return a;
}

#define MBAR_INIT(mb, cnt) \
    asm volatile("mbarrier.init.shared.b64 [%0], %1;" :: "r"(mb), "r"((uint32_t)(cnt)) : "memory")
#define MBAR_EXPECT(mb, bytes) \
    asm volatile("mbarrier.arrive.expect_tx.shared.b64 _, [%0], %1;" :: "r"(mb), "r"((uint32_t)(bytes)) : "memory")
#define MBAR_ARRIVE(mb) \
    asm volatile("mbarrier.arrive.shared.b64 _, [%0];" :: "r"(mb) : "memory")
#define MBAR_WAIT(mb, par) do { \
    uint32_t _m = (mb); uint32_t _p = (par); uint32_t _d; \
    asm volatile("{\n\t.reg .pred p;\n\t" \
        "mbarrier.try_wait.parity.acquire.cta.shared::cta.b64 p, [%1], %2;\n\t" \
        "selp.b32 %0, 1, 0, p;\n\t}" : "=r"(_d) : "r"(_m), "r"(_p) : "memory"); \
    if (!_d) { \
        asm volatile("{\n\t.reg .pred P1;\n\t" \
            "WL_%=:\n\t" \
            "mbarrier.try_wait.parity.acquire.cta.shared::cta.b64 P1, [%0], %1, 0x989680;\n\t" \
            "@P1 bra.uni WD_%=;\n\t" \
            "bra.uni WL_%=;\n\t" \
            "WD_%=:\n\t}" :: "r"(_m), "r"(_p) : "memory"); \
    } } while (0)

#define BULK_CP(dst, src, mb) \
    asm volatile("cp.async.bulk.shared::cluster.global.mbarrier::complete_tx::bytes [%0], [%1], %2, [%3];" \
        :: "r"((uint32_t)(dst)), "l"(src), "r"((uint32_t)16384), "r"((uint32_t)(mb)) : "memory")

#define LDSM4(r0, r1, r2, r3, a) \
    asm volatile("ldmatrix.sync.aligned.m8n8.x4.shared.b16 {%0,%1,%2,%3}, [%4];" \
        : "=r"(r0), "=r"(r1), "=r"(r2), "=r"(r3) : "r"(a))

#define MMA16816F(c0, c1, c2, c3, a0, a1, a2, a3, b0, b1) \
    asm volatile("mma.sync.aligned.m16n8k16.row.col.f32.f16.f16.f32 " \
        "{%0,%1,%2,%3},{%4,%5,%6,%7},{%8,%9},{%0,%1,%2,%3};" \
        : "+f"(c0), "+f"(c1), "+f"(c2), "+f"(c3) \
        : "r"(a0), "r"(a1), "r"(a2), "r"(a3), "r"(b0), "r"(b1))

// ---------------------------------------------------------------------------
__global__ void zero_kernel() {
    int i = blockIdx.x * blockDim.x + threadIdx.x;
    const int N = Bsz * NH;   // one buffer image (524288 halves)
    if (i == 0) g_bar = 0u;
    if (i < N) {
        g_c1[i] = 0.f; g_c2[i] = 0.f;
        __half z = __float2half(0.f);
        __half* h1 = &g_h1sw[0][0][0][0];
        __half* h2 = &g_h2sw[0][0][0][0];
        h1[i] = z; h1[N + i] = z;       // both ping-pong buffers
        h2[i] = z; h2[N + i] = z;
    }
}

// ---------------------------------------------------------------------------
// Weight conversion: gate-interleaved single fp16 plane, swizzled tiles.
// Column interleave (validated R4/R6/R8/R9).
// ---------------------------------------------------------------------------
__global__ void wconv_kernel(const float* __restrict__ src,
                             __half* __restrict__ dst) {
    int id = blockIdx.x * blockDim.x + threadIdx.x;
    int n  = id & 4095;
    int k0 = (id >> 12) * 8;

    int grp = n >> 5, w = n & 31;
    int half_ = w >> 4, idx = w & 15;
    int unit = grp * 8 + (idx >> 1);
    int gsel = half_ * 2 + (idx & 1);
    int scol = gsel * NH + unit;

    int nt = n >> 7, rl = n & 127;
    int kc = k0 >> 6, kl0 = k0 & 63;

    union { __half b[8]; uint4 v; } ph;
#pragma unroll
    for (int j = 0; j < 8; j++)
        ph.b[j] = __float2half_rn(src[(size_t)(k0 + j) * NH4 + scol]);

    size_t ib = (size_t)(nt * 32 + kc) * TILE_ELEMS;
    uint32_t off = (uint32_t)(rl * 128) + (uint32_t)((kl0 * 2) ^ ((rl & 7) << 4));
    *(uint4*)((char*)(dst + ib) + off) = ph.v;
}

// ---------------------------------------------------------------------------
// proj = relu(x @ W + b) -> single fp16 plane, swizzled tile images (as R9)
// ---------------------------------------------------------------------------
__global__ __launch_bounds__(256) void proj_kernel(
    const float* __restrict__ x, const float* __restrict__ W,
    const float* __restrict__ bh)
{
    __shared__ float As[16][128];
    __shared__ float Bs[16][128];

    const int tid = threadIdx.x;
    const int tx = tid & 15, ty = tid >> 4;
    const int r0 = blockIdx.y * 128;
    const int t  = r0 >> 9;
    const int b0 = r0 & 511;
    const int h0 = blockIdx.x * 128;

    float acc[8][8];
#pragma unroll
    for (int i = 0; i < 8; i++)
#pragma unroll
        for (int j = 0; j < 8; j++) acc[i][j] = 0.f;

    for (int ck = 0; ck < NIN / 16; ck++) {
        const int k0 = ck * 16;
#pragma unroll
        for (int L = 0; L < 2; L++) {
            int id  = tid + L * 256;
            int row = id >> 2, quad = id & 3;
            float4 v = *(const float4*)(x + ((size_t)(b0 + row) * Tsz + t) * NIN + k0 + quad * 4);
            As[quad * 4 + 0][row] = v.x; As[quad * 4 + 1][row] = v.y;
            As[quad * 4 + 2][row] = v.z; As[quad * 4 + 3][row] = v.w;
        }
#pragma unroll
        for (int L = 0; L < 2; L++) {
            int id = tid + L * 256;
            int kr = id >> 5, q = id & 31;
            *(float4*)&Bs[kr][q * 4] = *(const float4*)(W + (size_t)(k0 + kr) * NH + h0 + q * 4);
        }
        __syncthreads();
#pragma unroll
        for (int k = 0; k < 16; k++) {
            float a[8], bb[8];
            *(float4*)(a)      = *(const float4*)&As[k][ty * 8];
            *(float4*)(a + 4)  = *(const float4*)&As[k][ty * 8 + 4];
            *(float4*)(bb)     = *(const float4*)&Bs[k][tx * 8];
            *(float4*)(bb + 4) = *(const float4*)&Bs[k][tx * 8 + 4];
#pragma unroll
            for (int i = 0; i < 8; i++)
#pragma unroll
                for (int j = 0; j < 8; j++) acc[i][j] = fmaf(a[i], bb[j], acc[i][j]);
        }
        __syncthreads();
    }

    const int colbase = h0 + tx * 8;
    const int kc = colbase >> 6, kl0 = colbase & 63;
    __half* xsw = &g_xsw[0][0][0][0];
#pragma unroll
    for (int i = 0; i < 8; i++) {
        int b = b0 + ty * 8 + i;
        int mtL = b >> 7, rl = b & 127;
        union { __half e[8]; uint4 v; } ph;
#pragma unroll
        for (int j = 0; j < 8; j++) {
            float v = acc[i][j] + bh[colbase + j];
            v = v > 0.f ? v : 0.f;
            ph.e[j] = __float2half_rn(v);
        }
        size_t ib = ((size_t)(t * 4 + mtL) * 16 + kc) * TILE_ELEMS;
        uint32_t off = (uint32_t)(rl * 128) + (uint32_t)((kl0 * 2) ^ ((rl & 7) << 4));
        *(uint4*)((char*)(xsw + ib) + off) = ph.v;
    }
}

// ---------------------------------------------------------------------------
// Persistent 2-layer LSTM: 257 phases; phase p runs cell1(t=p) [p<256] and
// cell2(t=p-1) [p>=1] back-to-back per CTA (both depend only on phase p-1
// outputs). Grid 128 (1 CTA/SM, all resident), software grid barrier between
// phases. GEMM/epilogue identical to R9.
// ---------------------------------------------------------------------------
__global__ __launch_bounds__(288, 1) void lstm_persistent(
    const __half* __restrict__ xsw,
    __half* __restrict__ h1sw, __half* __restrict__ h2sw,
    const __half* __restrict__ w1, const __half* __restrict__ w2,
    const float* __restrict__ b1, const float* __restrict__ b2,
    float* __restrict__ c1, float* __restrict__ c2,
    float* __restrict__ out)
{
    extern __shared__ __align__(1024) char smem[];
    const int tid = threadIdx.x, lane = tid & 31, wid = tid >> 5;
    const int nt = blockIdx.x >> 2, mt = blockIdx.x & 3;
    const size_t IMG = (size_t)4 * 16 * TILE_ELEMS;

    const uint32_t sb = s2u(smem);
    const uint32_t CTRL = 196608;
    const uint32_t mb_full = sb + CTRL;          // 6 x 8B
    const uint32_t mb_cons = sb + CTRL + 48;     // 6 x 8B

    if (tid == 0) {
#pragma unroll
        for (int s = 0; s < 6; s++) {
            MBAR_INIT(mb_full + s * 8, 1);
            MBAR_INIT(mb_cons + s * 8, 256);
        }
    }
    __syncthreads();

    // consumer constants
    const int wm = wid >> 2, wn = wid & 3;
    const int l15 = lane & 15;
    const uint32_t khalf = (uint32_t)((lane >> 4) << 4);
    const uint32_t xr = (uint32_t)((l15 & 7) << 4);
    uint32_t baseA[4], baseB[2];
#pragma unroll
    for (int mi = 0; mi < 4; mi++) baseA[mi] = (uint32_t)((wm * 64 + mi * 16 + l15) * 128);
#pragma unroll
    for (int p2 = 0; p2 < 2; p2++) baseB[p2] = (uint32_t)((wn * 32 + p2 * 16 + l15) * 128);

    unsigned cg = 0;   // running chunk counter (identical on producer/consumers)

    for (int p = 0; p <= 256; p++) {
#pragma unroll 1
        for (int job = 0; job < 2; job++) {
            const bool valid = (job == 0) ? (p < 256) : (p >= 1);
            if (!valid) continue;

            const __half *Ax, *Ah, *Wk;
            const float* bias;
            float* cst;
            __half* Ho;
            float* op;
            if (job == 0) {            // cell1, t = p
                Ax = xsw + (size_t)p * IMG;
                Ah = h1sw + (size_t)((p + 1) & 1) * IMG;   // h1(t-1)
                Wk = w1; bias = b1; cst = c1;
                Ho = h1sw + (size_t)(p & 1) * IMG;
                op = nullptr;
            } else {                   // cell2, t = p-1
                Ax = h1sw + (size_t)((p - 1) & 1) * IMG;   // h1(t) from phase p-1
                Ah = h2sw + (size_t)((p - 1) & 1) * IMG;   // h2(t-1)
                Wk = w2; bias = b2; cst = c2;
                Ho = h2sw + (size_t)(p & 1) * IMG;
                op = (p == 256) ? out : nullptr;
            }

            if (tid == 256) {
                // ---------------- producer: 32 chunk loads ----------------
                unsigned g = cg;
                for (int c = 0; c < 32; c++, g++) {
                    const unsigned s = g % 6u, u = g / 6u;
                    if (g >= 6) MBAR_WAIT(mb_cons + s * 8, (u - 1) & 1);
                    const uint32_t base = sb + s * 32768u;
                    const __half* a_ = (c < 16)
                        ? Ax + (size_t)(mt * 16 + c) * TILE_ELEMS
                        : Ah + (size_t)(mt * 16 + c - 16) * TILE_ELEMS;
                    const __half* w_ = Wk + (size_t)(nt * 32 + c) * TILE_ELEMS;
                    const uint32_t mb = mb_full + s * 8;
                    MBAR_EXPECT(mb, 32768);
                    BULK_CP(base,         a_, mb);
                    BULK_CP(base + 16384, w_, mb);
                }
            } else if (wid < 8) {
                // ---------------- consumer: GEMM + fused epilogue ----------
                float acc[4][4][4];
#pragma unroll
                for (int mi = 0; mi < 4; mi++)
#pragma unroll
                    for (int nf = 0; nf < 4; nf++)
#pragma unroll
                        for (int cc = 0; cc < 4; cc++) acc[mi][nf][cc] = 0.f;

                unsigned g = cg;
                for (int c = 0; c < 32; c++, g++) {
                    const unsigned s = g % 6u, u = g / 6u;
                    MBAR_WAIT(mb_full + s * 8, u & 1);
                    const uint32_t stg = sb + s * 32768u;
                    const uint32_t aB = stg, wB = stg + 16384;

#pragma unroll
                    for (int k16 = 0; k16 < 4; k16++) {
                        const uint32_t kx = ((uint32_t)(k16 * 32) + khalf) ^ xr;

                        uint32_t a[4][4], bH[4][2];
#pragma unroll
                        for (int mi = 0; mi < 4; mi++)
                            LDSM4(a[mi][0], a[mi][1], a[mi][2], a[mi][3], aB + baseA[mi] + kx);
#pragma unroll
                        for (int pp = 0; pp < 2; pp++) {
                            uint32_t q0, q1, q2, q3;
                            LDSM4(q0, q1, q2, q3, wB + baseB[pp] + kx);
                            bH[2 * pp][0] = q0; bH[2 * pp][1] = q2;
                            bH[2 * pp + 1][0] = q1; bH[2 * pp + 1][1] = q3;
                        }
#pragma unroll
                        for (int mi = 0; mi < 4; mi++)
#pragma unroll
                            for (int nf = 0; nf < 4; nf++)
                                MMA16816F(acc[mi][nf][0], acc[mi][nf][1], acc[mi][nf][2], acc[mi][nf][3],
                                          a[mi][0], a[mi][1], a[mi][2], a[mi][3], bH[nf][0], bH[nf][1]);
                    }
                    MBAR_ARRIVE(mb_cons + s * 8);
                }

                // fused gate epilogue (identical math to R9)
                const int q = lane & 3, gg = lane >> 2;
                const int gbase = (nt * 4 + wn) * 8;
                float bi[2][4];
#pragma unroll
                for (int ue = 0; ue < 2; ue++) {
                    int u = gbase + q + 4 * ue;
                    bi[ue][0] = bias[u];
                    bi[ue][1] = bias[NH + u];
                    bi[ue][2] = bias[2 * NH + u] + 1.0f;   // FORGET_BIAS folded in
                    bi[ue][3] = bias[3 * NH + u];
                }

#pragma unroll
                for (int mi = 0; mi < 4; mi++) {
#pragma unroll
                    for (int d = 0; d < 2; d++) {
                        const int rl = wm * 64 + mi * 16 + gg + 8 * d;
                        const int rg = mt * 128 + rl;
#pragma unroll
                        for (int ue = 0; ue < 2; ue++) {
                            const int u = gbase + q + 4 * ue;
                            float zi = acc[mi][ue][2 * d + 0]     + bi[ue][0];
                            float zj = acc[mi][ue][2 * d + 1]     + bi[ue][1];
                            float zf = acc[mi][2 + ue][2 * d + 0] + bi[ue][2];
                            float zo = acc[mi][2 + ue][2 * d + 1] + bi[ue][3];

                            size_t ci = (size_t)rg * NH + u;
                            float cn = cst[ci] * sigf(zf) + sigf(zi) * tanhf(zj);
                            cst[ci] = cn;
                            float hv = tanhf(cn) * sigf(zo);

                            int kc = u >> 6, kl = u & 63;
                            size_t ib = (size_t)(mt * 16 + kc) * TILE_ELEMS;
                            uint32_t off = (uint32_t)(rl * 128) + (uint32_t)((kl * 2) ^ ((rl & 7) << 4));
                            *(__half*)((char*)(Ho + ib) + off) = __float2half_rn(hv);

                            if (op) op[ci] = hv;
                        }
                    }
                }
            }
            cg += 32;
        }

        // ---------------- grid-wide phase barrier ----------------
        __syncthreads();
        if (tid == 0) {
            __threadfence();
            atomicAdd(&g_bar, 1u);
            const unsigned tgt = (unsigned)NCTA * (unsigned)(p + 1);
            while (*((volatile unsigned*)&g_bar) < tgt) { }
            __threadfence();
        }
        __syncthreads();
    }
}

// ---------------------------------------------------------------------------
extern "C" void kernel_launch(void* const* d_in, const int* in_sizes, int n_in,
                              void* d_out, int out_size)
{
    const float* x  = (const float*)d_in[0];
    const float* W  = (const float*)d_in[1];
    const float* bh = (const float*)d_in[2];
    const float* k1 = (const float*)d_in[3];
    const float* b1 = (const float*)d_in[4];
    const float* k2 = (const float*)d_in[5];
    const float* b2 = (const float*)d_in[6];
    float* out = (float*)d_out;

    __half *xsw, *h1sw, *h2sw, *w1sw, *w2sw;
    float *c1, *c2;
    cudaGetSymbolAddress((void**)&xsw,  g_xsw);
    cudaGetSymbolAddress((void**)&h1sw, g_h1sw);
    cudaGetSymbolAddress((void**)&h2sw, g_h2sw);
    cudaGetSymbolAddress((void**)&w1sw, g_w1sw);
    cudaGetSymbolAddress((void**)&w2sw, g_w2sw);
    cudaGetSymbolAddress((void**)&c1,   g_c1);
    cudaGetSymbolAddress((void**)&c2,   g_c2);

    const int SMEM_BYTES = 196608 + 128;
    static bool attr_set = false;
    if (!attr_set) {
        cudaFuncSetAttribute(lstm_persistent,
                             cudaFuncAttributeMaxDynamicSharedMemorySize, SMEM_BYTES);
        attr_set = true;
    }

    zero_kernel<<<(Bsz * NH + 255) / 256, 256>>>();
    wconv_kernel<<<4096, 256>>>(k1, w1sw);
    wconv_kernel<<<4096, 256>>>(k2, w2sw);
    proj_kernel<<<dim3(8, (Tsz * Bsz) / 128), 256>>>(x, W, bh);

    lstm_persistent<<<NCTA, 288, SMEM_BYTES>>>(
        xsw, h1sw, h2sw, w1sw, w2sw, b1, b2, c1, c2, out);
}

// round 11
// speedup vs baseline: 10.7218x; 1.2777x over previous
#include <cuda_runtime.h>
#include <cuda_fp16.h>
#include <cstdint>
#include <math.h>

static constexpr int Bsz = 512;
static constexpr int Tsz = 256;
static constexpr int NIN = 128;
static constexpr int NH  = 1024;
static constexpr int NH4 = 4096;
static constexpr int TILE_ELEMS = 8192;    // 128 rows x 64 fp16 = 16KB
static constexpr int NCTA = 128;           // persistent grid (1 CTA/SM)

// ---------------- scratch (static device arrays) ----------------
__device__ __align__(16384) __half g_xsw [256][4][16][TILE_ELEMS];  // [t][mt][kc]
__device__ __align__(16384) __half g_h1sw[2][4][16][TILE_ELEMS];    // [buf][mt][kc]
__device__ __align__(16384) __half g_h2sw[2][4][16][TILE_ELEMS];
__device__ __align__(16384) __half g_w1sw[32][32][TILE_ELEMS];      // [nt][kc]
__device__ __align__(16384) __half g_w2sw[32][32][TILE_ELEMS];
__device__ float g_c1[Bsz * NH];           // relaid-out: [cta][tid][slot16]
__device__ float g_c2[Bsz * NH];
__device__ unsigned g_barm[4];             // per-mt phase epoch counters

// ---------------- helpers ----------------
__device__ __forceinline__ float sigf(float v) {
    return __fdividef(1.0f, 1.0f + __expf(-v));
}
// tanh via 1 - 2/(e^{2x}+1): overflow-safe (inf -> 1, 0 -> -1), err ~3e-7
__device__ __forceinline__ float tanhfast(float v) {
    return 1.0f - __fdividef(2.0f, __expf(2.0f * v) + 1.0f);
}

__device__ __forceinline__ uint32_t s2u(const void* p) {
    uint32_t a;
    asm("{ .reg .u64 t; cvta.to.shared.u64 t, %1; cvt.u32.u64 %0, t; }" : "=r"(a) : "l"(p));
    return a;
}

#define MBAR_INIT(mb, cnt) \
    asm volatile("mbarrier.init.shared.b64 [%0], %1;" :: "r"(mb), "r"((uint32_t)(cnt)) : "memory")
#define MBAR_EXPECT(mb, bytes) \
    asm volatile("mbarrier.arrive.expect_tx.shared.b64 _, [%0], %1;" :: "r"(mb), "r"((uint32_t)(bytes)) : "memory")
#define MBAR_ARRIVE(mb) \
    asm volatile("mbarrier.arrive.shared.b64 _, [%0];" :: "r"(mb) : "memory")
#define MBAR_WAIT(mb, par) do { \
    uint32_t _m = (mb); uint32_t _p = (par); uint32_t _d; \
    asm volatile("{\n\t.reg .pred p;\n\t" \
        "mbarrier.try_wait.parity.acquire.cta.shared::cta.b64 p, [%1], %2;\n\t" \
        "selp.b32 %0, 1, 0, p;\n\t}" : "=r"(_d) : "r"(_m), "r"(_p) : "memory"); \
    if (!_d) { \
        asm volatile("{\n\t.reg .pred P1;\n\t" \
            "WL_%=:\n\t" \
            "mbarrier.try_wait.parity.acquire.cta.shared::cta.b64 P1, [%0], %1, 0x989680;\n\t" \
            "@P1 bra.uni WD_%=;\n\t" \
            "bra.uni WL_%=;\n\t" \
            "WD_%=:\n\t}" :: "r"(_m), "r"(_p) : "memory"); \
    } } while (0)

#define BULK_CP(dst, src, mb) \
    asm volatile("cp.async.bulk.shared::cluster.global.mbarrier::complete_tx::bytes [%0], [%1], %2, [%3];" \
        :: "r"((uint32_t)(dst)), "l"(src), "r"((uint32_t)16384), "r"((uint32_t)(mb)) : "memory")

#define LDSM4(r0, r1, r2, r3, a) \
    asm volatile("ldmatrix.sync.aligned.m8n8.x4.shared.b16 {%0,%1,%2,%3}, [%4];" \
        : "=r"(r0), "=r"(r1), "=r"(r2), "=r"(r3) : "r"(a))

#define MMA16816F(c0, c1, c2, c3, a0, a1, a2, a3, b0, b1) \
    asm volatile("mma.sync.aligned.m16n8k16.row.col.f32.f16.f16.f32 " \
        "{%0,%1,%2,%3},{%4,%5,%6,%7},{%8,%9},{%0,%1,%2,%3};" \
        : "+f"(c0), "+f"(c1), "+f"(c2), "+f"(c3) \
        : "r"(a0), "r"(a1), "r"(a2), "r"(a3), "r"(b0), "r"(b1))

#define CONS_BAR() asm volatile("bar.sync 1, 256;" ::: "memory")

// ---------------------------------------------------------------------------
__global__ void zero_kernel() {
    int i = blockIdx.x * blockDim.x + threadIdx.x;
    const int N = Bsz * NH;   // one buffer image (524288 halves)
    if (i < 4) g_barm[i] = 0u;
    if (i < N) {
        g_c1[i] = 0.f; g_c2[i] = 0.f;
        __half z = __float2half(0.f);
        __half* h1 = &g_h1sw[0][0][0][0];
        __half* h2 = &g_h2sw[0][0][0][0];
        h1[i] = z; h1[N + i] = z;       // both ping-pong buffers
        h2[i] = z; h2[N + i] = z;
    }
}

// ---------------------------------------------------------------------------
// Weight conversion: gate-interleaved single fp16 plane, swizzled tiles.
// Column interleave (validated R4/R6/R8/R9/R10).
// ---------------------------------------------------------------------------
__global__ void wconv_kernel(const float* __restrict__ src,
                             __half* __restrict__ dst) {
    int id = blockIdx.x * blockDim.x + threadIdx.x;
    int n  = id & 4095;
    int k0 = (id >> 12) * 8;

    int grp = n >> 5, w = n & 31;
    int half_ = w >> 4, idx = w & 15;
    int unit = grp * 8 + (idx >> 1);
    int gsel = half_ * 2 + (idx & 1);
    int scol = gsel * NH + unit;

    int nt = n >> 7, rl = n & 127;
    int kc = k0 >> 6, kl0 = k0 & 63;

    union { __half b[8]; uint4 v; } ph;
#pragma unroll
    for (int j = 0; j < 8; j++)
        ph.b[j] = __float2half_rn(src[(size_t)(k0 + j) * NH4 + scol]);

    size_t ib = (size_t)(nt * 32 + kc) * TILE_ELEMS;
    uint32_t off = (uint32_t)(rl * 128) + (uint32_t)((kl0 * 2) ^ ((rl & 7) << 4));
    *(uint4*)((char*)(dst + ib) + off) = ph.v;
}

// ---------------------------------------------------------------------------
// proj = relu(x @ W + b) -> single fp16 plane, swizzled tile images (as R9)
// ---------------------------------------------------------------------------
__global__ __launch_bounds__(256) void proj_kernel(
    const float* __restrict__ x, const float* __restrict__ W,
    const float* __restrict__ bh)
{
    __shared__ float As[16][128];
    __shared__ float Bs[16][128];

    const int tid = threadIdx.x;
    const int tx = tid & 15, ty = tid >> 4;
    const int r0 = blockIdx.y * 128;
    const int t  = r0 >> 9;
    const int b0 = r0 & 511;
    const int h0 = blockIdx.x * 128;

    float acc[8][8];
#pragma unroll
    for (int i = 0; i < 8; i++)
#pragma unroll
        for (int j = 0; j < 8; j++) acc[i][j] = 0.f;

    for (int ck = 0; ck < NIN / 16; ck++) {
        const int k0 = ck * 16;
#pragma unroll
        for (int L = 0; L < 2; L++) {
            int id  = tid + L * 256;
            int row = id >> 2, quad = id & 3;
            float4 v = *(const float4*)(x + ((size_t)(b0 + row) * Tsz + t) * NIN + k0 + quad * 4);
            As[quad * 4 + 0][row] = v.x; As[quad * 4 + 1][row] = v.y;
            As[quad * 4 + 2][row] = v.z; As[quad * 4 + 3][row] = v.w;
        }
#pragma unroll
        for (int L = 0; L < 2; L++) {
            int id = tid + L * 256;
            int kr = id >> 5, q = id & 31;
            *(float4*)&Bs[kr][q * 4] = *(const float4*)(W + (size_t)(k0 + kr) * NH + h0 + q * 4);
        }
        __syncthreads();
#pragma unroll
        for (int k = 0; k < 16; k++) {
            float a[8], bb[8];
            *(float4*)(a)      = *(const float4*)&As[k][ty * 8];
            *(float4*)(a + 4)  = *(const float4*)&As[k][ty * 8 + 4];
            *(float4*)(bb)     = *(const float4*)&Bs[k][tx * 8];
            *(float4*)(bb + 4) = *(const float4*)&Bs[k][tx * 8 + 4];
#pragma unroll
            for (int i = 0; i < 8; i++)
#pragma unroll
                for (int j = 0; j < 8; j++) acc[i][j] = fmaf(a[i], bb[j], acc[i][j]);
        }
        __syncthreads();
    }

    const int colbase = h0 + tx * 8;
    const int kc = colbase >> 6, kl0 = colbase & 63;
    __half* xsw = &g_xsw[0][0][0][0];
#pragma unroll
    for (int i = 0; i < 8; i++) {
        int b = b0 + ty * 8 + i;
        int mtL = b >> 7, rl = b & 127;
        union { __half e[8]; uint4 v; } ph;
#pragma unroll
        for (int j = 0; j < 8; j++) {
            float v = acc[i][j] + bh[colbase + j];
            v = v > 0.f ? v : 0.f;
            ph.e[j] = __float2half_rn(v);
        }
        size_t ib = ((size_t)(t * 4 + mtL) * 16 + kc) * TILE_ELEMS;
        uint32_t off = (uint32_t)(rl * 128) + (uint32_t)((kl0 * 2) ^ ((rl & 7) << 4));
        *(uint4*)((char*)(xsw + ib) + off) = ph.v;
    }
}

// ---------------------------------------------------------------------------
// Persistent 2-layer LSTM, dataflow-synchronized:
//  - per-mt epoch counters (batch blocks are independent; 32-CTA domains)
//  - consumers NEVER spin: bar.sync(1,256) + tid0 posts epoch, then continue
//  - producer (tid 256) free-runs; spins on the epoch only before the first
//    h-dependent chunk; prefetches the static x-half across phase boundaries
//  - GEMM inner loop / swizzle / pipeline protocol identical to R10
// ---------------------------------------------------------------------------
__global__ __launch_bounds__(288, 1) void lstm_persistent(
    const __half* __restrict__ xsw,
    __half* __restrict__ h1sw, __half* __restrict__ h2sw,
    const __half* __restrict__ w1, const __half* __restrict__ w2,
    const float* __restrict__ b1, const float* __restrict__ b2,
    float* __restrict__ c1, float* __restrict__ c2,
    float* __restrict__ out)
{
    extern __shared__ __align__(1024) char smem[];
    const int tid = threadIdx.x, lane = tid & 31, wid = tid >> 5;
    const int nt = blockIdx.x >> 2, mt = blockIdx.x & 3;
    const size_t IMG = (size_t)4 * 16 * TILE_ELEMS;

    const uint32_t sb = s2u(smem);
    const uint32_t CTRL = 196608;
    const uint32_t mb_full = sb + CTRL;          // 6 x 8B
    const uint32_t mb_cons = sb + CTRL + 48;     // 6 x 8B

    if (tid == 0) {
#pragma unroll
        for (int s = 0; s < 6; s++) {
            MBAR_INIT(mb_full + s * 8, 1);
            MBAR_INIT(mb_cons + s * 8, 256);
        }
    }
    __syncthreads();

    // ======================= producer =======================
    if (tid == 256) {
        volatile unsigned* barm = (volatile unsigned*)&g_barm[mt];
        unsigned g = 0;
        for (int p = 0; p <= 256; p++) {
            if (p < 256) {   // job0: cell1(t=p)
                const __half* Ax = xsw + (size_t)p * IMG;
                const __half* Ah = h1sw + (size_t)((p + 1) & 1) * IMG;
                for (int c = 0; c < 32; c++, g++) {
                    if (c == 16) {       // h1(p-1) readiness epoch
                        const unsigned tgt = 32u * (unsigned)p;
                        while (*barm < tgt) { }
                        __threadfence();
                    }
                    const unsigned s = g % 6u, u = g / 6u;
                    if (g >= 6) MBAR_WAIT(mb_cons + s * 8, (u - 1) & 1);
                    const uint32_t base = sb + s * 32768u;
                    const __half* a_ = (c < 16)
                        ? Ax + (size_t)(mt * 16 + c) * TILE_ELEMS
                        : Ah + (size_t)(mt * 16 + c - 16) * TILE_ELEMS;
                    const __half* w_ = w1 + (size_t)(nt * 32 + c) * TILE_ELEMS;
                    const uint32_t mb = mb_full + s * 8;
                    MBAR_EXPECT(mb, 32768);
                    BULK_CP(base,         a_, mb);
                    BULK_CP(base + 16384, w_, mb);
                }
            }
            if (p >= 1) {    // job1: cell2(t=p-1)
                if (p == 256) {          // job0 skipped: take the epoch here
                    const unsigned tgt = 32u * 256u;
                    while (*barm < tgt) { }
                    __threadfence();
                }
                const __half* Ax = h1sw + (size_t)((p - 1) & 1) * IMG;
                const __half* Ah = h2sw + (size_t)((p - 1) & 1) * IMG;
                for (int c = 0; c < 32; c++, g++) {
                    const unsigned s = g % 6u, u = g / 6u;
                    if (g >= 6) MBAR_WAIT(mb_cons + s * 8, (u - 1) & 1);
                    const uint32_t base = sb + s * 32768u;
                    const __half* a_ = (c < 16)
                        ? Ax + (size_t)(mt * 16 + c) * TILE_ELEMS
                        : Ah + (size_t)(mt * 16 + c - 16) * TILE_ELEMS;
                    const __half* w_ = w2 + (size_t)(nt * 32 + c) * TILE_ELEMS;
                    const uint32_t mb = mb_full + s * 8;
                    MBAR_EXPECT(mb, 32768);
                    BULK_CP(base,         a_, mb);
                    BULK_CP(base + 16384, w_, mb);
                }
            }
        }
        return;
    }
    if (wid >= 8) return;

    // ======================= consumers =======================
    const int wm = wid >> 2, wn = wid & 3;
    const int l15 = lane & 15;
    const uint32_t khalf = (uint32_t)((lane >> 4) << 4);
    const uint32_t xr = (uint32_t)((l15 & 7) << 4);
    uint32_t baseA[4], baseB[2];
#pragma unroll
    for (int mi = 0; mi < 4; mi++) baseA[mi] = (uint32_t)((wm * 64 + mi * 16 + l15) * 128);
#pragma unroll
    for (int p2 = 0; p2 < 2; p2++) baseB[p2] = (uint32_t)((wn * 32 + p2 * 16 + l15) * 128);

    unsigned cg = 0;   // running chunk counter (matches producer order)

    for (int p = 0; p <= 256; p++) {
#pragma unroll 1
        for (int job = 0; job < 2; job++) {
            const bool valid = (job == 0) ? (p < 256) : (p >= 1);
            if (!valid) continue;

            const float* bias;
            float* cst;
            __half* Ho;
            float* op;
            if (job == 0) {            // cell1, t = p
                bias = b1; cst = c1;
                Ho = h1sw + (size_t)(p & 1) * IMG;
                op = nullptr;
            } else {                   // cell2, t = p-1
                bias = b2; cst = c2;
                Ho = h2sw + (size_t)(p & 1) * IMG;
                op = (p == 256) ? out : nullptr;
            }

            float acc[4][4][4];
#pragma unroll
            for (int mi = 0; mi < 4; mi++)
#pragma unroll
                for (int nf = 0; nf < 4; nf++)
#pragma unroll
                    for (int cc = 0; cc < 4; cc++) acc[mi][nf][cc] = 0.f;

            unsigned g = cg;
            for (int c = 0; c < 32; c++, g++) {
                const unsigned s = g % 6u, u = g / 6u;
                MBAR_WAIT(mb_full + s * 8, u & 1);
                const uint32_t stg = sb + s * 32768u;
                const uint32_t aB = stg, wB = stg + 16384;

#pragma unroll
                for (int k16 = 0; k16 < 4; k16++) {
                    const uint32_t kx = ((uint32_t)(k16 * 32) + khalf) ^ xr;

                    uint32_t a[4][4], bH[4][2];
#pragma unroll
                    for (int mi = 0; mi < 4; mi++)
                        LDSM4(a[mi][0], a[mi][1], a[mi][2], a[mi][3], aB + baseA[mi] + kx);
#pragma unroll
                    for (int pp = 0; pp < 2; pp++) {
                        uint32_t q0, q1, q2, q3;
                        LDSM4(q0, q1, q2, q3, wB + baseB[pp] + kx);
                        bH[2 * pp][0] = q0; bH[2 * pp][1] = q2;
                        bH[2 * pp + 1][0] = q1; bH[2 * pp + 1][1] = q3;
                    }
#pragma unroll
                    for (int mi = 0; mi < 4; mi++)
#pragma unroll
                        for (int nf = 0; nf < 4; nf++)
                            MMA16816F(acc[mi][nf][0], acc[mi][nf][1], acc[mi][nf][2], acc[mi][nf][3],
                                      a[mi][0], a[mi][1], a[mi][2], a[mi][3], bH[nf][0], bH[nf][1]);
                }
                MBAR_ARRIVE(mb_cons + s * 8);
            }
            cg += 32;

            // ---------- fused gate epilogue (vector c-state) ----------
            const int q = lane & 3, gg = lane >> 2;
            const int gbase = (nt * 4 + wn) * 8;
            float bi[2][4];
#pragma unroll
            for (int ue = 0; ue < 2; ue++) {
                int u = gbase + q + 4 * ue;
                bi[ue][0] = bias[u];
                bi[ue][1] = bias[NH + u];
                bi[ue][2] = bias[2 * NH + u] + 1.0f;   // FORGET_BIAS folded in
                bi[ue][3] = bias[3 * NH + u];
            }

            // thread-private c slots: [cta][tid][16], slot = mi*4 + d*2 + ue
            float* cvec = cst + ((size_t)blockIdx.x * 256 + tid) * 16;
            float cva[16];
#pragma unroll
            for (int v = 0; v < 4; v++)
                *(float4*)(cva + 4 * v) = ((const float4*)cvec)[v];

#pragma unroll
            for (int mi = 0; mi < 4; mi++) {
#pragma unroll
                for (int d = 0; d < 2; d++) {
                    const int rl = wm * 64 + mi * 16 + gg + 8 * d;
                    const int rg = mt * 128 + rl;
#pragma unroll
                    for (int ue = 0; ue < 2; ue++) {
                        const int u = gbase + q + 4 * ue;
                        float zi = acc[mi][ue][2 * d + 0]     + bi[ue][0];
                        float zj = acc[mi][ue][2 * d + 1]     + bi[ue][1];
                        float zf = acc[mi][2 + ue][2 * d + 0] + bi[ue][2];
                        float zo = acc[mi][2 + ue][2 * d + 1] + bi[ue][3];

                        const int slot = mi * 4 + d * 2 + ue;
                        float cn = cva[slot] * sigf(zf) + sigf(zi) * tanhfast(zj);
                        cva[slot] = cn;
                        float hv = tanhfast(cn) * sigf(zo);

                        int kc = u >> 6, kl = u & 63;
                        size_t ib = (size_t)(mt * 16 + kc) * TILE_ELEMS;
                        uint32_t off = (uint32_t)(rl * 128) + (uint32_t)((kl * 2) ^ ((rl & 7) << 4));
                        *(__half*)((char*)(Ho + ib) + off) = __float2half_rn(hv);

                        if (op) op[(size_t)rg * NH + u] = hv;
                    }
                }
            }
#pragma unroll
            for (int v = 0; v < 4; v++)
                ((float4*)cvec)[v] = *(float4*)(cva + 4 * v);
        }

        // ---------- post epoch; do NOT wait ----------
        CONS_BAR();
        if (tid == 0) {
            __threadfence();
            atomicAdd(&g_barm[mt], 1u);
        }
    }
}

// ---------------------------------------------------------------------------
extern "C" void kernel_launch(void* const* d_in, const int* in_sizes, int n_in,
                              void* d_out, int out_size)
{
    const float* x  = (const float*)d_in[0];
    const float* W  = (const float*)d_in[1];
    const float* bh = (const float*)d_in[2];
    const float* k1 = (const float*)d_in[3];
    const float* b1 = (const float*)d_in[4];
    const float* k2 = (const float*)d_in[5];
    const float* b2 = (const float*)d_in[6];
    float* out = (float*)d_out;

    __half *xsw, *h1sw, *h2sw, *w1sw, *w2sw;
    float *c1, *c2;
    cudaGetSymbolAddress((void**)&xsw,  g_xsw);
    cudaGetSymbolAddress((void**)&h1sw, g_h1sw);
    cudaGetSymbolAddress((void**)&h2sw, g_h2sw);
    cudaGetSymbolAddress((void**)&w1sw, g_w1sw);
    cudaGetSymbolAddress((void**)&w2sw, g_w2sw);
    cudaGetSymbolAddress((void**)&c1,   g_c1);
    cudaGetSymbolAddress((void**)&c2,   g_c2);

    const int SMEM_BYTES = 196608 + 128;
    static bool attr_set = false;
    if (!attr_set) {
        cudaFuncSetAttribute(lstm_persistent,
                             cudaFuncAttributeMaxDynamicSharedMemorySize, SMEM_BYTES);
        attr_set = true;
    }

    zero_kernel<<<(Bsz * NH + 255) / 256, 256>>>();
    wconv_kernel<<<4096, 256>>>(k1, w1sw);
    wconv_kernel<<<4096, 256>>>(k2, w2sw);
    proj_kernel<<<dim3(8, (Tsz * Bsz) / 128), 256>>>(x, W, bh);

    lstm_persistent<<<NCTA, 288, SMEM_BYTES>>>(
        xsw, h1sw, h2sw, w1sw, w2sw, b1, b2, c1, c2, out);
}

// round 15
// speedup vs baseline: 10.9250x; 1.0189x over previous
#include <cuda_runtime.h>
#include <cuda_fp16.h>
#include <cstdint>
#include <math.h>

static constexpr int Bsz = 512;
static constexpr int Tsz = 256;
static constexpr int NIN = 128;
static constexpr int NH  = 1024;
static constexpr int NH4 = 4096;
static constexpr int TILE_ELEMS = 8192;    // 128 rows x 64 fp16 = 16KB
static constexpr int NCTA = 128;           // persistent grid (1 CTA/SM)

// ---------------- scratch (static device arrays) ----------------
__device__ __align__(16384) __half g_xsw [256][4][16][TILE_ELEMS];  // proj out [t][mt][kc]
__device__ __align__(16384) __half g_xin [2][256][4][2][TILE_ELEMS];// x hi/lo [t][mt][kc]
__device__ __align__(16384) __half g_whid[2][8][2][TILE_ELEMS];     // W_hidden hi/lo [nt][kc]
__device__ __align__(16384) __half g_h1sw[3][4][16][TILE_ELEMS];    // triple buffer [buf][mt][kc]
__device__ __align__(16384) __half g_h2sw[2][4][16][TILE_ELEMS];
__device__ __align__(16384) __half g_w1sw[32][32][TILE_ELEMS];      // [nt][kc]
__device__ __align__(16384) __half g_w2sw[32][32][TILE_ELEMS];
__device__ float g_c1[Bsz * NH];           // [cta][tid][slot16]
__device__ float g_c2[Bsz * NH];
__device__ unsigned g_barm[4];             // single per-mt phase epoch (R11 semantics)

// ---------------- helpers ----------------
__device__ __forceinline__ float sigf(float v) {
    return __fdividef(1.0f, 1.0f + __expf(-v));
}
__device__ __forceinline__ float tanhfast(float v) {
    return 1.0f - __fdividef(2.0f, __expf(2.0f * v) + 1.0f);
}

__device__ __forceinline__ uint32_t s2u(const void* p) {
    uint32_t a;
    asm("{ .reg .u64 t; cvta.to.shared.u64 t, %1; cvt.u32.u64 %0, t; }" : "=r"(a) : "l"(p));
    return a;
}

#define MBAR_INIT(mb, cnt) \
    asm volatile("mbarrier.init.shared.b64 [%0], %1;" :: "r"(mb), "r"((uint32_t)(cnt)) : "memory")
#define MBAR_EXPECT(mb, bytes) \
    asm volatile("mbarrier.arrive.expect_tx.shared.b64 _, [%0], %1;" :: "r"(mb), "r"((uint32_t)(bytes)) : "memory")
#define MBAR_ARRIVE(mb) \
    asm volatile("mbarrier.arrive.shared.b64 _, [%0];" :: "r"(mb) : "memory")
#define MBAR_WAIT(mb, par) do { \
    uint32_t _m = (mb); uint32_t _p = (par); uint32_t _d; \
    asm volatile("{\n\t.reg .pred p;\n\t" \
        "mbarrier.try_wait.parity.acquire.cta.shared::cta.b64 p, [%1], %2;\n\t" \
        "selp.b32 %0, 1, 0, p;\n\t}" : "=r"(_d) : "r"(_m), "r"(_p) : "memory"); \
    if (!_d) { \
        asm volatile("{\n\t.reg .pred P1;\n\t" \
            "WL_%=:\n\t" \
            "mbarrier.try_wait.parity.acquire.cta.shared::cta.b64 P1, [%0], %1, 0x989680;\n\t" \
            "@P1 bra.uni WD_%=;\n\t" \
            "bra.uni WL_%=;\n\t" \
            "WD_%=:\n\t}" :: "r"(_m), "r"(_p) : "memory"); \
    } } while (0)

#define BULK_CP(dst, src, mb) \
    asm volatile("cp.async.bulk.shared::cluster.global.mbarrier::complete_tx::bytes [%0], [%1], %2, [%3];" \
        :: "r"((uint32_t)(dst)), "l"(src), "r"((uint32_t)16384), "r"((uint32_t)(mb)) : "memory")

#define LDSM4(r0, r1, r2, r3, a) \
    asm volatile("ldmatrix.sync.aligned.m8n8.x4.shared.b16 {%0,%1,%2,%3}, [%4];" \
        : "=r"(r0), "=r"(r1), "=r"(r2), "=r"(r3) : "r"(a))

#define MMA16816F(c0, c1, c2, c3, a0, a1, a2, a3, b0, b1) \
    asm volatile("mma.sync.aligned.m16n8k16.row.col.f32.f16.f16.f32 " \
        "{%0,%1,%2,%3},{%4,%5,%6,%7},{%8,%9},{%0,%1,%2,%3};" \
        : "+f"(c0), "+f"(c1), "+f"(c2), "+f"(c3) \
        : "r"(a0), "r"(a1), "r"(a2), "r"(a3), "r"(b0), "r"(b1))

#define CONS_BAR() asm volatile("bar.sync 1, 256;" ::: "memory")

// ---------------------------------------------------------------------------
__global__ void zero_kernel() {
    int i = blockIdx.x * blockDim.x + threadIdx.x;
    const int N = Bsz * NH;
    if (i < 4) g_barm[i] = 0u;
    if (i < N) {
        g_c1[i] = 0.f; g_c2[i] = 0.f;
        __half z = __float2half(0.f);
        __half* h1 = &g_h1sw[0][0][0][0];
        __half* h2 = &g_h2sw[0][0][0][0];
        h1[i] = z; h1[N + i] = z; h1[2 * (size_t)N + i] = z;
        h2[i] = z; h2[N + i] = z;
    }
}

// ---------------------------------------------------------------------------
// Recurrent-weight conversion (gate-interleaved, validated R4..R11)
// ---------------------------------------------------------------------------
__global__ void wconv_kernel(const float* __restrict__ src,
                             __half* __restrict__ dst) {
    int id = blockIdx.x * blockDim.x + threadIdx.x;
    int n  = id & 4095;
    int k0 = (id >> 12) * 8;

    int grp = n >> 5, w = n & 31;
    int half_ = w >> 4, idx = w & 15;
    int unit = grp * 8 + (idx >> 1);
    int gsel = half_ * 2 + (idx & 1);
    int scol = gsel * NH + unit;

    int nt = n >> 7, rl = n & 127;
    int kc = k0 >> 6, kl0 = k0 & 63;

    union { __half b[8]; uint4 v; } ph;
#pragma unroll
    for (int j = 0; j < 8; j++)
        ph.b[j] = __float2half_rn(src[(size_t)(k0 + j) * NH4 + scol]);

    size_t ib = (size_t)(nt * 32 + kc) * TILE_ELEMS;
    uint32_t off = (uint32_t)(rl * 128) + (uint32_t)((kl0 * 2) ^ ((rl & 7) << 4));
    *(uint4*)((char*)(dst + ib) + off) = ph.v;
}

// ---------------------------------------------------------------------------
// W_hidden conversion: hi/lo planes, swizzled [nt 8][kc 2] tiles
// ---------------------------------------------------------------------------
__global__ void wconvh_kernel(const float* __restrict__ src) {
    int id = blockIdx.x * blockDim.x + threadIdx.x;   // 1024 n x 16 octets
    int n  = id & 1023;
    int k0 = (id >> 10) * 8;

    int nt = n >> 7, rl = n & 127;
    int kc = k0 >> 6, kl0 = k0 & 63;

    union { __half b[8]; uint4 v; } ph, pl;
#pragma unroll
    for (int j = 0; j < 8; j++) {
        float wv = src[(size_t)(k0 + j) * NH + n];
        __half h = __float2half_rn(wv);
        ph.b[j] = h;
        pl.b[j] = __float2half_rn(wv - __half2float(h));
    }
    uint32_t off = (uint32_t)(rl * 128) + (uint32_t)((kl0 * 2) ^ ((rl & 7) << 4));
    *(uint4*)((char*)&g_whid[0][nt][kc][0] + off) = ph.v;
    *(uint4*)((char*)&g_whid[1][nt][kc][0] + off) = pl.v;
}

// ---------------------------------------------------------------------------
// x conversion: fp32 [B,T,NIN] -> hi/lo fp16 swizzled tiles [t][mt][kc]
// ---------------------------------------------------------------------------
__global__ void xconv_kernel(const float* __restrict__ x) {
    int id = blockIdx.x * blockDim.x + threadIdx.x;   // t(256) x b(512) x oct(16)
    int oct = id & 15;
    int b   = (id >> 4) & 511;
    int t   = id >> 13;
    int k0  = oct * 8;

    const float* src = x + ((size_t)b * Tsz + t) * NIN + k0;
    union { __half e[8]; uint4 v; } ph, pl;
#pragma unroll
    for (int j = 0; j < 8; j++) {
        float v = src[j];
        __half h = __float2half_rn(v);
        ph.e[j] = h;
        pl.e[j] = __float2half_rn(v - __half2float(h));
    }
    int mt = b >> 7, rl = b & 127;
    int kc = k0 >> 6, kl0 = k0 & 63;
    uint32_t off = (uint32_t)(rl * 128) + (uint32_t)((kl0 * 2) ^ ((rl & 7) << 4));
    *(uint4*)((char*)&g_xin[0][t][mt][kc][0] + off) = ph.v;
    *(uint4*)((char*)&g_xin[1][t][mt][kc][0] + off) = pl.v;
}

// ---------------------------------------------------------------------------
// proj via HMMA: relu( x @ W_hidden + b ), 3-pass hi/lo (fp32-accurate).
// Grid (8 nt, 16 tslab), 288 thr. W resident in smem; 4-stage A ring.
// ---------------------------------------------------------------------------
__global__ __launch_bounds__(288, 1) void proj_hmma(const float* __restrict__ bh) {
    extern __shared__ __align__(1024) char smem[];
    const int tid = threadIdx.x, lane = tid & 31, wid = tid >> 5;
    const int nt = blockIdx.x, tslab = blockIdx.y;
    const uint32_t sb = s2u(smem);
    const uint32_t WOFF = 131072;             // 4 stages x 32KB before this
    const uint32_t CTRL = 196608;
    const uint32_t mb_full = sb + CTRL;       // 4 x 8B
    const uint32_t mb_cons = sb + CTRL + 32;  // 4 x 8B
    const uint32_t mb_w    = sb + CTRL + 64;

    if (tid == 0) {
#pragma unroll
        for (int s = 0; s < 4; s++) {
            MBAR_INIT(mb_full + s * 8, 1);
            MBAR_INIT(mb_cons + s * 8, 256);
        }
        MBAR_INIT(mb_w, 1);
    }
    __syncthreads();

    if (tid == 256) {
        MBAR_EXPECT(mb_w, 65536);
        BULK_CP(sb + WOFF,         &g_whid[0][nt][0][0], mb_w);
        BULK_CP(sb + WOFF + 16384, &g_whid[0][nt][1][0], mb_w);
        BULK_CP(sb + WOFF + 32768, &g_whid[1][nt][0][0], mb_w);
        BULK_CP(sb + WOFF + 49152, &g_whid[1][nt][1][0], mb_w);
        unsigned g = 0;
        for (int j = 0; j < 64; j++) {
            const int r = tslab * 64 + j, t = r >> 2, mt = r & 3;
            for (int kc = 0; kc < 2; kc++, g++) {
                const unsigned s = g & 3u, u = g >> 2;
                if (g >= 4) MBAR_WAIT(mb_cons + s * 8, (u - 1) & 1);
                const uint32_t base = sb + s * 32768u;
                const uint32_t mb = mb_full + s * 8;
                MBAR_EXPECT(mb, 32768);
                BULK_CP(base,         &g_xin[0][t][mt][kc][0], mb);
                BULK_CP(base + 16384, &g_xin[1][t][mt][kc][0], mb);
            }
        }
        return;
    }
    if (wid >= 8) return;

    const int wm = wid >> 2, wn = wid & 3;
    const int l15 = lane & 15;
    const uint32_t khalf = (uint32_t)((lane >> 4) << 4);
    const uint32_t xr = (uint32_t)((l15 & 7) << 4);
    uint32_t baseA[4], baseB[2];
#pragma unroll
    for (int mi = 0; mi < 4; mi++) baseA[mi] = (uint32_t)((wm * 64 + mi * 16 + l15) * 128);
#pragma unroll
    for (int p2 = 0; p2 < 2; p2++) baseB[p2] = (uint32_t)((wn * 32 + p2 * 16 + l15) * 128);

    const int q = lane & 3, gg = lane >> 2;
    float bv[4][2];
#pragma unroll
    for (int nf = 0; nf < 4; nf++) {
        int col = nt * 128 + wn * 32 + nf * 8 + 2 * q;
        bv[nf][0] = bh[col];
        bv[nf][1] = bh[col + 1];
    }

    MBAR_WAIT(mb_w, 0);

    unsigned g = 0;
    for (int j = 0; j < 64; j++) {
        const int r = tslab * 64 + j, t = r >> 2, mt = r & 3;

        float acc[4][4][4];
#pragma unroll
        for (int mi = 0; mi < 4; mi++)
#pragma unroll
            for (int nf = 0; nf < 4; nf++)
#pragma unroll
                for (int cc = 0; cc < 4; cc++) acc[mi][nf][cc] = 0.f;

        for (int kc = 0; kc < 2; kc++, g++) {
            const unsigned s = g & 3u, u = g >> 2;
            MBAR_WAIT(mb_full + s * 8, u & 1);
            const uint32_t stg = sb + s * 32768u;
            const uint32_t ahB = stg, alB = stg + 16384;
            const uint32_t whB = sb + WOFF + (uint32_t)kc * 16384;
            const uint32_t wlB = sb + WOFF + 32768 + (uint32_t)kc * 16384;

#pragma unroll
            for (int k16 = 0; k16 < 4; k16++) {
                const uint32_t kx = ((uint32_t)(k16 * 32) + khalf) ^ xr;

                uint32_t ah[4][4], al[4][4], bH[4][2], bL[4][2];
#pragma unroll
                for (int mi = 0; mi < 4; mi++)
                    LDSM4(ah[mi][0], ah[mi][1], ah[mi][2], ah[mi][3], ahB + baseA[mi] + kx);
#pragma unroll
                for (int pp = 0; pp < 2; pp++) {
                    uint32_t q0, q1, q2, q3;
                    LDSM4(q0, q1, q2, q3, whB + baseB[pp] + kx);
                    bH[2 * pp][0] = q0; bH[2 * pp][1] = q2;
                    bH[2 * pp + 1][0] = q1; bH[2 * pp + 1][1] = q3;
                }
#pragma unroll
                for (int mi = 0; mi < 4; mi++)
#pragma unroll
                    for (int nf = 0; nf < 4; nf++)
                        MMA16816F(acc[mi][nf][0], acc[mi][nf][1], acc[mi][nf][2], acc[mi][nf][3],
                                  ah[mi][0], ah[mi][1], ah[mi][2], ah[mi][3], bH[nf][0], bH[nf][1]);
#pragma unroll
                for (int mi = 0; mi < 4; mi++)
                    LDSM4(al[mi][0], al[mi][1], al[mi][2], al[mi][3], alB + baseA[mi] + kx);
#pragma unroll
                for (int mi = 0; mi < 4; mi++)
#pragma unroll
                    for (int nf = 0; nf < 4; nf++)
                        MMA16816F(acc[mi][nf][0], acc[mi][nf][1], acc[mi][nf][2], acc[mi][nf][3],
                                  al[mi][0], al[mi][1], al[mi][2], al[mi][3], bH[nf][0], bH[nf][1]);
#pragma unroll
                for (int pp = 0; pp < 2; pp++) {
                    uint32_t q0, q1, q2, q3;
                    LDSM4(q0, q1, q2, q3, wlB + baseB[pp] + kx);
                    bL[2 * pp][0] = q0; bL[2 * pp][1] = q2;
                    bL[2 * pp + 1][0] = q1; bL[2 * pp + 1][1] = q3;
                }
#pragma unroll
                for (int mi = 0; mi < 4; mi++)
#pragma unroll
                    for (int nf = 0; nf < 4; nf++)
                        MMA16816F(acc[mi][nf][0], acc[mi][nf][1], acc[mi][nf][2], acc[mi][nf][3],
                                  ah[mi][0], ah[mi][1], ah[mi][2], ah[mi][3], bL[nf][0], bL[nf][1]);
            }
            MBAR_ARRIVE(mb_cons + s * 8);
        }

#pragma unroll
        for (int mi = 0; mi < 4; mi++) {
#pragma unroll
            for (int d = 0; d < 2; d++) {
                const int rl = wm * 64 + mi * 16 + gg + 8 * d;
#pragma unroll
                for (int nf = 0; nf < 4; nf++) {
                    int col = nt * 128 + wn * 32 + nf * 8 + 2 * q;
                    float v0 = acc[mi][nf][2 * d + 0] + bv[nf][0];
                    float v1 = acc[mi][nf][2 * d + 1] + bv[nf][1];
                    v0 = v0 > 0.f ? v0 : 0.f;
                    v1 = v1 > 0.f ? v1 : 0.f;
                    __half2 hh = __floats2half2_rn(v0, v1);
                    int kcg = col >> 6, klo = col & 63;
                    uint32_t off = (uint32_t)(rl * 128) + (uint32_t)((klo * 2) ^ ((rl & 7) << 4));
                    *(__half2*)((char*)&g_xsw[t][mt][kcg][0] + off) = hh;
                }
            }
        }
    }
}

// ---------------------------------------------------------------------------
// Persistent 2-layer LSTM, SINGLE phase-end epoch (R11 semantics, proven),
// h1 triple-buffered.
// ---------------------------------------------------------------------------
__global__ __launch_bounds__(288, 1) void lstm_persistent(
    const __half* __restrict__ xsw,
    __half* __restrict__ h1sw, __half* __restrict__ h2sw,
    const __half* __restrict__ w1, const __half* __restrict__ w2,
    const float* __restrict__ b1, const float* __restrict__ b2,
    float* __restrict__ c1, float* __restrict__ c2,
    float* __restrict__ out)
{
    extern __shared__ __align__(1024) char smem[];
    const int tid = threadIdx.x, lane = tid & 31, wid = tid >> 5;
    const int nt = blockIdx.x >> 2, mt = blockIdx.x & 3;
    const size_t IMG = (size_t)4 * 16 * TILE_ELEMS;

    const uint32_t sb = s2u(smem);
    const uint32_t CTRL = 196608;
    const uint32_t mb_full = sb + CTRL;          // 6 x 8B
    const uint32_t mb_cons = sb + CTRL + 48;     // 6 x 8B

    if (tid == 0) {
#pragma unroll
        for (int s = 0; s < 6; s++) {
            MBAR_INIT(mb_full + s * 8, 1);
            MBAR_INIT(mb_cons + s * 8, 256);
        }
    }
    __syncthreads();

    // ======================= producer =======================
    if (tid == 256) {
        volatile unsigned* barm = (volatile unsigned*)&g_barm[mt];
        unsigned g = 0;
        for (int p = 0; p <= 256; p++) {
            const int h1rd = (p + 2) % 3;      // (p-1) mod 3
            if (p < 256) {   // job0: cell1(t=p)
                const __half* Ax = xsw + (size_t)p * IMG;
                const __half* Ah = h1sw + (size_t)h1rd * IMG;
                for (int c = 0; c < 32; c++, g++) {
                    if (c == 16) {       // phase p-1 fully done
                        const unsigned tgt = 32u * (unsigned)p;
                        while (*barm < tgt) { }
                        __threadfence();
                    }
                    const unsigned s = g % 6u, u = g / 6u;
                    if (g >= 6) MBAR_WAIT(mb_cons + s * 8, (u - 1) & 1);
                    const uint32_t base = sb + s * 32768u;
                    const __half* a_ = (c < 16)
                        ? Ax + (size_t)(mt * 16 + c) * TILE_ELEMS
                        : Ah + (size_t)(mt * 16 + c - 16) * TILE_ELEMS;
                    const __half* w_ = w1 + (size_t)(nt * 32 + c) * TILE_ELEMS;
                    const uint32_t mb = mb_full + s * 8;
                    MBAR_EXPECT(mb, 32768);
                    BULK_CP(base,         a_, mb);
                    BULK_CP(base + 16384, w_, mb);
                }
            }
            if (p >= 1) {    // job1: cell2(t=p-1)
                const __half* Ax = h1sw + (size_t)h1rd * IMG;   // h1(p-1)
                const __half* Ah = h2sw + (size_t)((p - 1) & 1) * IMG;
                for (int c = 0; c < 32; c++, g++) {
                    if (p == 256 && c == 0) {        // job0 skipped: phase 255 done
                        const unsigned tgt = 32u * 256u;
                        while (*barm < tgt) { }
                        __threadfence();
                    }
                    if (c == 16) {                   // phase p-1 fully done
                        const unsigned tgt = 32u * (unsigned)p;
                        while (*barm < tgt) { }
                        __threadfence();
                    }
                    const unsigned s = g % 6u, u = g / 6u;
                    if (g >= 6) MBAR_WAIT(mb_cons + s * 8, (u - 1) & 1);
                    const uint32_t base = sb + s * 32768u;
                    const __half* a_ = (c < 16)
                        ? Ax + (size_t)(mt * 16 + c) * TILE_ELEMS
                        : Ah + (size_t)(mt * 16 + c - 16) * TILE_ELEMS;
                    const __half* w_ = w2 + (size_t)(nt * 32 + c) * TILE_ELEMS;
                    const uint32_t mb = mb_full + s * 8;
                    MBAR_EXPECT(mb, 32768);
                    BULK_CP(base,         a_, mb);
                    BULK_CP(base + 16384, w_, mb);
                }
            }
        }
        return;
    }
    if (wid >= 8) return;

    // ======================= consumers =======================
    const int wm = wid >> 2, wn = wid & 3;
    const int l15 = lane & 15;
    const uint32_t khalf = (uint32_t)((lane >> 4) << 4);
    const uint32_t xr = (uint32_t)((l15 & 7) << 4);
    uint32_t baseA[4], baseB[2];
#pragma unroll
    for (int mi = 0; mi < 4; mi++) baseA[mi] = (uint32_t)((wm * 64 + mi * 16 + l15) * 128);
#pragma unroll
    for (int p2 = 0; p2 < 2; p2++) baseB[p2] = (uint32_t)((wn * 32 + p2 * 16 + l15) * 128);

    unsigned cg = 0;

    for (int p = 0; p <= 256; p++) {
#pragma unroll 1
        for (int job = 0; job < 2; job++) {
            const bool valid = (job == 0) ? (p < 256) : (p >= 1);
            if (!valid) continue;

            const float* bias;
            float* cst;
            __half* Ho;
            float* op;
            if (job == 0) {
                bias = b1; cst = c1;
                Ho = h1sw + (size_t)(p % 3) * IMG;
                op = nullptr;
            } else {
                bias = b2; cst = c2;
                Ho = h2sw + (size_t)(p & 1) * IMG;
                op = (p == 256) ? out : nullptr;
            }

            float acc[4][4][4];
#pragma unroll
            for (int mi = 0; mi < 4; mi++)
#pragma unroll
                for (int nf = 0; nf < 4; nf++)
#pragma unroll
                    for (int cc = 0; cc < 4; cc++) acc[mi][nf][cc] = 0.f;

            unsigned g = cg;
            for (int c = 0; c < 32; c++, g++) {
                const unsigned s = g % 6u, u = g / 6u;
                MBAR_WAIT(mb_full + s * 8, u & 1);
                const uint32_t stg = sb + s * 32768u;
                const uint32_t aB = stg, wB = stg + 16384;

#pragma unroll
                for (int k16 = 0; k16 < 4; k16++) {
                    const uint32_t kx = ((uint32_t)(k16 * 32) + khalf) ^ xr;

                    uint32_t a[4][4], bH[4][2];
#pragma unroll
                    for (int mi = 0; mi < 4; mi++)
                        LDSM4(a[mi][0], a[mi][1], a[mi][2], a[mi][3], aB + baseA[mi] + kx);
#pragma unroll
                    for (int pp = 0; pp < 2; pp++) {
                        uint32_t q0, q1, q2, q3;
                        LDSM4(q0, q1, q2, q3, wB + baseB[pp] + kx);
                        bH[2 * pp][0] = q0; bH[2 * pp][1] = q2;
                        bH[2 * pp + 1][0] = q1; bH[2 * pp + 1][1] = q3;
                    }
#pragma unroll
                    for (int mi = 0; mi < 4; mi++)
#pragma unroll
                        for (int nf = 0; nf < 4; nf++)
                            MMA16816F(acc[mi][nf][0], acc[mi][nf][1], acc[mi][nf][2], acc[mi][nf][3],
                                      a[mi][0], a[mi][1], a[mi][2], a[mi][3], bH[nf][0], bH[nf][1]);
                }
                MBAR_ARRIVE(mb_cons + s * 8);
            }
            cg += 32;

            // ---------- fused gate epilogue ----------
            const int q = lane & 3, gg = lane >> 2;
            const int gbase = (nt * 4 + wn) * 8;
            float bi[2][4];
#pragma unroll
            for (int ue = 0; ue < 2; ue++) {
                int u = gbase + q + 4 * ue;
                bi[ue][0] = bias[u];
                bi[ue][1] = bias[NH + u];
                bi[ue][2] = bias[2 * NH + u] + 1.0f;
                bi[ue][3] = bias[3 * NH + u];
            }

            float* cvec = cst + ((size_t)blockIdx.x * 256 + tid) * 16;
            float cva[16];
#pragma unroll
            for (int v = 0; v < 4; v++)
                *(float4*)(cva + 4 * v) = ((const float4*)cvec)[v];

#pragma unroll
            for (int mi = 0; mi < 4; mi++) {
#pragma unroll
                for (int d = 0; d < 2; d++) {
                    const int rl = wm * 64 + mi * 16 + gg + 8 * d;
                    const int rg = mt * 128 + rl;
#pragma unroll
                    for (int ue = 0; ue < 2; ue++) {
                        const int u = gbase + q + 4 * ue;
                        float zi = acc[mi][ue][2 * d + 0]     + bi[ue][0];
                        float zj = acc[mi][ue][2 * d + 1]     + bi[ue][1];
                        float zf = acc[mi][2 + ue][2 * d + 0] + bi[ue][2];
                        float zo = acc[mi][2 + ue][2 * d + 1] + bi[ue][3];

                        const int slot = mi * 4 + d * 2 + ue;
                        float cn = cva[slot] * sigf(zf) + sigf(zi) * tanhfast(zj);
                        cva[slot] = cn;
                        float hv = tanhfast(cn) * sigf(zo);

                        int kc = u >> 6, kl = u & 63;
                        size_t ib = (size_t)(mt * 16 + kc) * TILE_ELEMS;
                        uint32_t off = (uint32_t)(rl * 128) + (uint32_t)((kl * 2) ^ ((rl & 7) << 4));
                        *(__half*)((char*)(Ho + ib) + off) = __float2half_rn(hv);

                        if (op) op[(size_t)rg * NH + u] = hv;
                    }
                }
            }
#pragma unroll
            for (int v = 0; v < 4; v++)
                ((float4*)cvec)[v] = *(float4*)(cva + 4 * v);
        }

        // ---------- single per-phase epoch post (R11 semantics) ----------
        CONS_BAR();
        if (tid == 0) {
            __threadfence();
            atomicAdd(&g_barm[mt], 1u);
        }
    }
}

// ---------------------------------------------------------------------------
extern "C" void kernel_launch(void* const* d_in, const int* in_sizes, int n_in,
                              void* d_out, int out_size)
{
    const float* x  = (const float*)d_in[0];
    const float* W  = (const float*)d_in[1];
    const float* bh = (const float*)d_in[2];
    const float* k1 = (const float*)d_in[3];
    const float* b1 = (const float*)d_in[4];
    const float* k2 = (const float*)d_in[5];
    const float* b2 = (const float*)d_in[6];
    float* out = (float*)d_out;

    __half *xsw, *h1sw, *h2sw, *w1sw, *w2sw;
    float *c1, *c2;
    cudaGetSymbolAddress((void**)&xsw,  g_xsw);
    cudaGetSymbolAddress((void**)&h1sw, g_h1sw);
    cudaGetSymbolAddress((void**)&h2sw, g_h2sw);
    cudaGetSymbolAddress((void**)&w1sw, g_w1sw);
    cudaGetSymbolAddress((void**)&w2sw, g_w2sw);
    cudaGetSymbolAddress((void**)&c1,   g_c1);
    cudaGetSymbolAddress((void**)&c2,   g_c2);

    const int SMEM_BYTES = 196608 + 128;
    static bool attr_set = false;
    if (!attr_set) {
        cudaFuncSetAttribute(lstm_persistent,
                             cudaFuncAttributeMaxDynamicSharedMemorySize, SMEM_BYTES);
        cudaFuncSetAttribute(proj_hmma,
                             cudaFuncAttributeMaxDynamicSharedMemorySize, SMEM_BYTES);
        attr_set = true;
    }

    zero_kernel<<<(Bsz * NH + 255) / 256, 256>>>();
    wconv_kernel<<<4096, 256>>>(k1, w1sw);
    wconv_kernel<<<4096, 256>>>(k2, w2sw);
    wconvh_kernel<<<64, 256>>>(W);
    xconv_kernel<<<8192, 256>>>(x);
    proj_hmma<<<dim3(8, 16), 288, SMEM_BYTES>>>(bh);

    lstm_persistent<<<NCTA, 288, SMEM_BYTES>>>(
        xsw, h1sw, h2sw, w1sw, w2sw, b1, b2, c1, c2, out);
}

// round 16
// speedup vs baseline: 12.1837x; 1.1152x over previous
#include <cuda_runtime.h>
#include <cuda_fp16.h>
#include <cstdint>
#include <math.h>

static constexpr int Bsz = 512;
static constexpr int Tsz = 256;
static constexpr int NIN = 128;
static constexpr int NH  = 1024;
static constexpr int NH4 = 4096;
static constexpr int TILE_ELEMS = 8192;    // 128 rows x 64 fp16 = 16KB
static constexpr int NCTA = 128;           // persistent grid (1 CTA/SM)

// ---------------- scratch (static device arrays) ----------------
__device__ __align__(16384) __half g_xsw [256][4][16][TILE_ELEMS];  // proj out [t][mt][kc]
__device__ __align__(16384) __half g_xin [256][4][2][TILE_ELEMS];   // x fp16 [t][mt][kc]
__device__ __align__(16384) __half g_whid[2][8][2][TILE_ELEMS];     // W_hidden hi/lo [nt][kc]
__device__ __align__(16384) __half g_h1sw[3][4][16][TILE_ELEMS];    // triple buffer
__device__ __align__(16384) __half g_h2sw[2][4][16][TILE_ELEMS];
__device__ __align__(16384) __half g_w1sw[32][32][TILE_ELEMS];      // [nt][kc]
__device__ __align__(16384) __half g_w2sw[32][32][TILE_ELEMS];
__device__ float g_c1[Bsz * NH];           // [cta][tid][slot16]
__device__ float g_c2[Bsz * NH];
__device__ unsigned g_barm[4];             // single per-mt phase epoch (R11/R15 semantics)

// ---------------- helpers ----------------
__device__ __forceinline__ float sigf(float v) {
    return __fdividef(1.0f, 1.0f + __expf(-v));
}
__device__ __forceinline__ float tanhfast(float v) {
    return 1.0f - __fdividef(2.0f, __expf(2.0f * v) + 1.0f);
}

__device__ __forceinline__ uint32_t s2u(const void* p) {
    uint32_t a;
    asm("{ .reg .u64 t; cvta.to.shared.u64 t, %1; cvt.u32.u64 %0, t; }" : "=r"(a) : "l"(p));
    return a;
}

#define MBAR_INIT(mb, cnt) \
    asm volatile("mbarrier.init.shared.b64 [%0], %1;" :: "r"(mb), "r"((uint32_t)(cnt)) : "memory")
#define MBAR_EXPECT(mb, bytes) \
    asm volatile("mbarrier.arrive.expect_tx.shared.b64 _, [%0], %1;" :: "r"(mb), "r"((uint32_t)(bytes)) : "memory")
#define MBAR_ARRIVE(mb) \
    asm volatile("mbarrier.arrive.shared.b64 _, [%0];" :: "r"(mb) : "memory")
#define MBAR_WAIT(mb, par) do { \
    uint32_t _m = (mb); uint32_t _p = (par); uint32_t _d; \
    asm volatile("{\n\t.reg .pred p;\n\t" \
        "mbarrier.try_wait.parity.acquire.cta.shared::cta.b64 p, [%1], %2;\n\t" \
        "selp.b32 %0, 1, 0, p;\n\t}" : "=r"(_d) : "r"(_m), "r"(_p) : "memory"); \
    if (!_d) { \
        asm volatile("{\n\t.reg .pred P1;\n\t" \
            "WL_%=:\n\t" \
            "mbarrier.try_wait.parity.acquire.cta.shared::cta.b64 P1, [%0], %1, 0x989680;\n\t" \
            "@P1 bra.uni WD_%=;\n\t" \
            "bra.uni WL_%=;\n\t" \
            "WD_%=:\n\t}" :: "r"(_m), "r"(_p) : "memory"); \
    } } while (0)

#define BULK_CP(dst, src, mb) \
    asm volatile("cp.async.bulk.shared::cluster.global.mbarrier::complete_tx::bytes [%0], [%1], %2, [%3];" \
        :: "r"((uint32_t)(dst)), "l"(src), "r"((uint32_t)16384), "r"((uint32_t)(mb)) : "memory")

#define LDSM4(r0, r1, r2, r3, a) \
    asm volatile("ldmatrix.sync.aligned.m8n8.x4.shared.b16 {%0,%1,%2,%3}, [%4];" \
        : "=r"(r0), "=r"(r1), "=r"(r2), "=r"(r3) : "r"(a))

#define MMA16816F(c0, c1, c2, c3, a0, a1, a2, a3, b0, b1) \
    asm volatile("mma.sync.aligned.m16n8k16.row.col.f32.f16.f16.f32 " \
        "{%0,%1,%2,%3},{%4,%5,%6,%7},{%8,%9},{%0,%1,%2,%3};" \
        : "+f"(c0), "+f"(c1), "+f"(c2), "+f"(c3) \
        : "r"(a0), "r"(a1), "r"(a2), "r"(a3), "r"(b0), "r"(b1))

#define CONS_BAR() asm volatile("bar.sync 1, 256;" ::: "memory")

// fragment load for 64KB stage: [A0 16K | A1 16K | W0 16K | W1 16K], k16 0..7
__device__ __forceinline__ void load_frags(
    uint32_t aF[4][4], uint32_t bF[4][2], uint32_t stg, int k16,
    const uint32_t baseA[4], const uint32_t baseB[2], uint32_t khalf, uint32_t xr)
{
    const uint32_t kx = (uint32_t)((k16 >> 2) * 16384)
                      + ((((uint32_t)(k16 & 3)) * 32u + khalf) ^ xr);
#pragma unroll
    for (int mi = 0; mi < 4; mi++)
        LDSM4(aF[mi][0], aF[mi][1], aF[mi][2], aF[mi][3], stg + kx + baseA[mi]);
#pragma unroll
    for (int pp = 0; pp < 2; pp++) {
        uint32_t q0, q1, q2, q3;
        LDSM4(q0, q1, q2, q3, stg + 32768 + kx + baseB[pp]);
        bF[2 * pp][0] = q0; bF[2 * pp][1] = q2;
        bF[2 * pp + 1][0] = q1; bF[2 * pp + 1][1] = q3;
    }
}

__device__ __forceinline__ void mma_block(
    float acc[4][4][4], const uint32_t aF[4][4], const uint32_t bF[4][2])
{
#pragma unroll
    for (int mi = 0; mi < 4; mi++)
#pragma unroll
        for (int nf = 0; nf < 4; nf++)
            MMA16816F(acc[mi][nf][0], acc[mi][nf][1], acc[mi][nf][2], acc[mi][nf][3],
                      aF[mi][0], aF[mi][1], aF[mi][2], aF[mi][3], bF[nf][0], bF[nf][1]);
}

// ---------------------------------------------------------------------------
__global__ void zero_kernel() {
    int i = blockIdx.x * blockDim.x + threadIdx.x;
    const int N = Bsz * NH;
    if (i < 4) g_barm[i] = 0u;
    if (i < N) {
        g_c1[i] = 0.f; g_c2[i] = 0.f;
        __half z = __float2half(0.f);
        __half* h1 = &g_h1sw[0][0][0][0];
        __half* h2 = &g_h2sw[0][0][0][0];
        h1[i] = z; h1[N + i] = z; h1[2 * (size_t)N + i] = z;
        h2[i] = z; h2[N + i] = z;
    }
}

// ---------------------------------------------------------------------------
// Recurrent-weight conversion (gate-interleaved, validated R4..R15)
// ---------------------------------------------------------------------------
__global__ void wconv_kernel(const float* __restrict__ src,
                             __half* __restrict__ dst) {
    int id = blockIdx.x * blockDim.x + threadIdx.x;
    int n  = id & 4095;
    int k0 = (id >> 12) * 8;

    int grp = n >> 5, w = n & 31;
    int half_ = w >> 4, idx = w & 15;
    int unit = grp * 8 + (idx >> 1);
    int gsel = half_ * 2 + (idx & 1);
    int scol = gsel * NH + unit;

    int nt = n >> 7, rl = n & 127;
    int kc = k0 >> 6, kl0 = k0 & 63;

    union { __half b[8]; uint4 v; } ph;
#pragma unroll
    for (int j = 0; j < 8; j++)
        ph.b[j] = __float2half_rn(src[(size_t)(k0 + j) * NH4 + scol]);

    size_t ib = (size_t)(nt * 32 + kc) * TILE_ELEMS;
    uint32_t off = (uint32_t)(rl * 128) + (uint32_t)((kl0 * 2) ^ ((rl & 7) << 4));
    *(uint4*)((char*)(dst + ib) + off) = ph.v;
}

// ---------------------------------------------------------------------------
// W_hidden conversion: hi/lo planes, swizzled [nt 8][kc 2] tiles
// ---------------------------------------------------------------------------
__global__ void wconvh_kernel(const float* __restrict__ src) {
    int id = blockIdx.x * blockDim.x + threadIdx.x;
    int n  = id & 1023;
    int k0 = (id >> 10) * 8;

    int nt = n >> 7, rl = n & 127;
    int kc = k0 >> 6, kl0 = k0 & 63;

    union { __half b[8]; uint4 v; } ph, pl;
#pragma unroll
    for (int j = 0; j < 8; j++) {
        float wv = src[(size_t)(k0 + j) * NH + n];
        __half h = __float2half_rn(wv);
        ph.b[j] = h;
        pl.b[j] = __float2half_rn(wv - __half2float(h));
    }
    uint32_t off = (uint32_t)(rl * 128) + (uint32_t)((kl0 * 2) ^ ((rl & 7) << 4));
    *(uint4*)((char*)&g_whid[0][nt][kc][0] + off) = ph.v;
    *(uint4*)((char*)&g_whid[1][nt][kc][0] + off) = pl.v;
}

// ---------------------------------------------------------------------------
// x conversion: fp32 [B,T,NIN] -> single fp16 plane, swizzled [t][mt][kc]
// ---------------------------------------------------------------------------
__global__ void xconv_kernel(const float* __restrict__ x) {
    int id = blockIdx.x * blockDim.x + threadIdx.x;
    int oct = id & 15;
    int b   = (id >> 4) & 511;
    int t   = id >> 13;
    int k0  = oct * 8;

    const float* src = x + ((size_t)b * Tsz + t) * NIN + k0;
    union { __half e[8]; uint4 v; } ph;
#pragma unroll
    for (int j = 0; j < 8; j++)
        ph.e[j] = __float2half_rn(src[j]);

    int mt = b >> 7, rl = b & 127;
    int kc = k0 >> 6, kl0 = k0 & 63;
    uint32_t off = (uint32_t)(rl * 128) + (uint32_t)((kl0 * 2) ^ ((rl & 7) << 4));
    *(uint4*)((char*)&g_xin[t][mt][kc][0] + off) = ph.v;
}

// ---------------------------------------------------------------------------
// proj via HMMA: relu( x @ W_hidden + b ), 2-pass (x fp16, W hi/lo).
// Grid (8 nt, 16 tslab), 288 thr. W resident; 4-stage 16KB A ring.
// ---------------------------------------------------------------------------
__global__ __launch_bounds__(288, 1) void proj_hmma(const float* __restrict__ bh) {
    extern __shared__ __align__(1024) char smem[];
    const int tid = threadIdx.x, lane = tid & 31, wid = tid >> 5;
    const int nt = blockIdx.x, tslab = blockIdx.y;
    const uint32_t sb = s2u(smem);
    const uint32_t WOFF = 65536;              // 4 stages x 16KB before this
    const uint32_t CTRL = 196608;
    const uint32_t mb_full = sb + CTRL;       // 4 x 8B
    const uint32_t mb_cons = sb + CTRL + 32;  // 4 x 8B
    const uint32_t mb_w    = sb + CTRL + 64;

    if (tid == 0) {
#pragma unroll
        for (int s = 0; s < 4; s++) {
            MBAR_INIT(mb_full + s * 8, 1);
            MBAR_INIT(mb_cons + s * 8, 256);
        }
        MBAR_INIT(mb_w, 1);
    }
    __syncthreads();

    if (tid == 256) {
        MBAR_EXPECT(mb_w, 65536);
        BULK_CP(sb + WOFF,         &g_whid[0][nt][0][0], mb_w);
        BULK_CP(sb + WOFF + 16384, &g_whid[0][nt][1][0], mb_w);
        BULK_CP(sb + WOFF + 32768, &g_whid[1][nt][0][0], mb_w);
        BULK_CP(sb + WOFF + 49152, &g_whid[1][nt][1][0], mb_w);
        unsigned g = 0;
        for (int j = 0; j < 64; j++) {
            const int r = tslab * 64 + j, t = r >> 2, mt = r & 3;
            for (int kc = 0; kc < 2; kc++, g++) {
                const unsigned s = g & 3u, u = g >> 2;
                if (g >= 4) MBAR_WAIT(mb_cons + s * 8, (u - 1) & 1);
                const uint32_t base = sb + s * 16384u;
                const uint32_t mb = mb_full + s * 8;
                MBAR_EXPECT(mb, 16384);
                BULK_CP(base, &g_xin[t][mt][kc][0], mb);
            }
        }
        return;
    }
    if (wid >= 8) return;

    const int wm = wid >> 2, wn = wid & 3;
    const int l15 = lane & 15;
    const uint32_t khalf = (uint32_t)((lane >> 4) << 4);
    const uint32_t xr = (uint32_t)((l15 & 7) << 4);
    uint32_t baseA[4], baseB[2];
#pragma unroll
    for (int mi = 0; mi < 4; mi++) baseA[mi] = (uint32_t)((wm * 64 + mi * 16 + l15) * 128);
#pragma unroll
    for (int p2 = 0; p2 < 2; p2++) baseB[p2] = (uint32_t)((wn * 32 + p2 * 16 + l15) * 128);

    const int q = lane & 3, gg = lane >> 2;
    float bv[4][2];
#pragma unroll
    for (int nf = 0; nf < 4; nf++) {
        int col = nt * 128 + wn * 32 + nf * 8 + 2 * q;
        bv[nf][0] = bh[col];
        bv[nf][1] = bh[col + 1];
    }

    MBAR_WAIT(mb_w, 0);

    unsigned g = 0;
    for (int j = 0; j < 64; j++) {
        const int r = tslab * 64 + j, t = r >> 2, mt = r & 3;

        float acc[4][4][4];
#pragma unroll
        for (int mi = 0; mi < 4; mi++)
#pragma unroll
            for (int nf = 0; nf < 4; nf++)
#pragma unroll
                for (int cc = 0; cc < 4; cc++) acc[mi][nf][cc] = 0.f;

        for (int kc = 0; kc < 2; kc++, g++) {
            const unsigned s = g & 3u, u = g >> 2;
            MBAR_WAIT(mb_full + s * 8, u & 1);
            const uint32_t aB  = sb + s * 16384u;
            const uint32_t whB = sb + WOFF + (uint32_t)kc * 16384;
            const uint32_t wlB = sb + WOFF + 32768 + (uint32_t)kc * 16384;

#pragma unroll
            for (int k16 = 0; k16 < 4; k16++) {
                const uint32_t kx = ((uint32_t)(k16 * 32) + khalf) ^ xr;

                uint32_t ah[4][4], bH[4][2], bL[4][2];
#pragma unroll
                for (int mi = 0; mi < 4; mi++)
                    LDSM4(ah[mi][0], ah[mi][1], ah[mi][2], ah[mi][3], aB + baseA[mi] + kx);
#pragma unroll
                for (int pp = 0; pp < 2; pp++) {
                    uint32_t q0, q1, q2, q3;
                    LDSM4(q0, q1, q2, q3, whB + baseB[pp] + kx);
                    bH[2 * pp][0] = q0; bH[2 * pp][1] = q2;
                    bH[2 * pp + 1][0] = q1; bH[2 * pp + 1][1] = q3;
                }
#pragma unroll
                for (int mi = 0; mi < 4; mi++)
#pragma unroll
                    for (int nf = 0; nf < 4; nf++)
                        MMA16816F(acc[mi][nf][0], acc[mi][nf][1], acc[mi][nf][2], acc[mi][nf][3],
                                  ah[mi][0], ah[mi][1], ah[mi][2], ah[mi][3], bH[nf][0], bH[nf][1]);
#pragma unroll
                for (int pp = 0; pp < 2; pp++) {
                    uint32_t q0, q1, q2, q3;
                    LDSM4(q0, q1, q2, q3, wlB + baseB[pp] + kx);
                    bL[2 * pp][0] = q0; bL[2 * pp][1] = q2;
                    bL[2 * pp + 1][0] = q1; bL[2 * pp + 1][1] = q3;
                }
#pragma unroll
                for (int mi = 0; mi < 4; mi++)
#pragma unroll
                    for (int nf = 0; nf < 4; nf++)
                        MMA16816F(acc[mi][nf][0], acc[mi][nf][1], acc[mi][nf][2], acc[mi][nf][3],
                                  ah[mi][0], ah[mi][1], ah[mi][2], ah[mi][3], bL[nf][0], bL[nf][1]);
            }
            MBAR_ARRIVE(mb_cons + s * 8);
        }

#pragma unroll
        for (int mi = 0; mi < 4; mi++) {
#pragma unroll
            for (int d = 0; d < 2; d++) {
                const int rl = wm * 64 + mi * 16 + gg + 8 * d;
#pragma unroll
                for (int nf = 0; nf < 4; nf++) {
                    int col = nt * 128 + wn * 32 + nf * 8 + 2 * q;
                    float v0 = acc[mi][nf][2 * d + 0] + bv[nf][0];
                    float v1 = acc[mi][nf][2 * d + 1] + bv[nf][1];
                    v0 = v0 > 0.f ? v0 : 0.f;
                    v1 = v1 > 0.f ? v1 : 0.f;
                    __half2 hh = __floats2half2_rn(v0, v1);
                    int kcg = col >> 6, klo = col & 63;
                    uint32_t off = (uint32_t)(rl * 128) + (uint32_t)((klo * 2) ^ ((rl & 7) << 4));
                    *(__half2*)((char*)&g_xsw[t][mt][kcg][0] + off) = hh;
                }
            }
        }
    }
}

// ---------------------------------------------------------------------------
// Persistent 2-layer LSTM: R15 sync semantics (single phase epoch), 64KB
// chunks (16/job), 3-stage ring, register fragment rotation.
// ---------------------------------------------------------------------------
__global__ __launch_bounds__(288, 1) void lstm_persistent(
    const __half* __restrict__ xsw,
    __half* __restrict__ h1sw, __half* __restrict__ h2sw,
    const __half* __restrict__ w1, const __half* __restrict__ w2,
    const float* __restrict__ b1, const float* __restrict__ b2,
    float* __restrict__ c1, float* __restrict__ c2,
    float* __restrict__ out)
{
    extern __shared__ __align__(1024) char smem[];
    const int tid = threadIdx.x, lane = tid & 31, wid = tid >> 5;
    const int nt = blockIdx.x >> 2, mt = blockIdx.x & 3;
    const size_t IMG = (size_t)4 * 16 * TILE_ELEMS;

    const uint32_t sb = s2u(smem);
    const uint32_t CTRL = 196608;
    const uint32_t mb_full = sb + CTRL;          // 3 x 8B
    const uint32_t mb_cons = sb + CTRL + 32;     // 3 x 8B

    if (tid == 0) {
#pragma unroll
        for (int s = 0; s < 3; s++) {
            MBAR_INIT(mb_full + s * 8, 1);
            MBAR_INIT(mb_cons + s * 8, 256);
        }
    }
    __syncthreads();

    // ======================= producer =======================
    if (tid == 256) {
        volatile unsigned* barm = (volatile unsigned*)&g_barm[mt];
        unsigned g = 0;
        for (int p = 0; p <= 256; p++) {
            const int h1rd = (p + 2) % 3;
            if (p < 256) {   // job0: cell1(t=p)
                const __half* Ax = xsw + (size_t)p * IMG;
                const __half* Ah = h1sw + (size_t)h1rd * IMG;
                for (int cc = 0; cc < 16; cc++, g++) {
                    if (cc == 8) {
                        const unsigned tgt = 32u * (unsigned)p;
                        while (*barm < tgt) { }
                        __threadfence();
                    }
                    const unsigned s = g % 3u, u = g / 3u;
                    if (g >= 3) MBAR_WAIT(mb_cons + s * 8, (u - 1) & 1);
                    const uint32_t base = sb + s * 65536u;
                    const int kcl = (cc < 8) ? 2 * cc : 2 * cc - 16;
                    const __half* A = (cc < 8) ? Ax : Ah;
                    const uint32_t mb = mb_full + s * 8;
                    MBAR_EXPECT(mb, 65536);
                    BULK_CP(base,         A  + (size_t)(mt * 16 + kcl)     * TILE_ELEMS, mb);
                    BULK_CP(base + 16384, A  + (size_t)(mt * 16 + kcl + 1) * TILE_ELEMS, mb);
                    BULK_CP(base + 32768, w1 + (size_t)(nt * 32 + 2 * cc)     * TILE_ELEMS, mb);
                    BULK_CP(base + 49152, w1 + (size_t)(nt * 32 + 2 * cc + 1) * TILE_ELEMS, mb);
                }
            }
            if (p >= 1) {    // job1: cell2(t=p-1)
                const __half* Ax = h1sw + (size_t)h1rd * IMG;
                const __half* Ah = h2sw + (size_t)((p - 1) & 1) * IMG;
                for (int cc = 0; cc < 16; cc++, g++) {
                    if (p == 256 && cc == 0) {
                        const unsigned tgt = 32u * 256u;
                        while (*barm < tgt) { }
                        __threadfence();
                    }
                    if (cc == 8) {
                        const unsigned tgt = 32u * (unsigned)p;
                        while (*barm < tgt) { }
                        __threadfence();
                    }
                    const unsigned s = g % 3u, u = g / 3u;
                    if (g >= 3) MBAR_WAIT(mb_cons + s * 8, (u - 1) & 1);
                    const uint32_t base = sb + s * 65536u;
                    const int kcl = (cc < 8) ? 2 * cc : 2 * cc - 16;
                    const __half* A = (cc < 8) ? Ax : Ah;
                    const uint32_t mb = mb_full + s * 8;
                    MBAR_EXPECT(mb, 65536);
                    BULK_CP(base,         A  + (size_t)(mt * 16 + kcl)     * TILE_ELEMS, mb);
                    BULK_CP(base + 16384, A  + (size_t)(mt * 16 + kcl + 1) * TILE_ELEMS, mb);
                    BULK_CP(base + 32768, w2 + (size_t)(nt * 32 + 2 * cc)     * TILE_ELEMS, mb);
                    BULK_CP(base + 49152, w2 + (size_t)(nt * 32 + 2 * cc + 1) * TILE_ELEMS, mb);
                }
            }
        }
        return;
    }
    if (wid >= 8) return;

    // ======================= consumers =======================
    const int wm = wid >> 2, wn = wid & 3;
    const int l15 = lane & 15;
    const uint32_t khalf = (uint32_t)((lane >> 4) << 4);
    const uint32_t xr = (uint32_t)((l15 & 7) << 4);
    uint32_t baseA[4], baseB[2];
#pragma unroll
    for (int mi = 0; mi < 4; mi++) baseA[mi] = (uint32_t)((wm * 64 + mi * 16 + l15) * 128);
#pragma unroll
    for (int p2 = 0; p2 < 2; p2++) baseB[p2] = (uint32_t)((wn * 32 + p2 * 16 + l15) * 128);

    unsigned cg = 0;

    for (int p = 0; p <= 256; p++) {
#pragma unroll 1
        for (int job = 0; job < 2; job++) {
            const bool valid = (job == 0) ? (p < 256) : (p >= 1);
            if (!valid) continue;

            const float* bias;
            float* cst;
            __half* Ho;
            float* op;
            if (job == 0) {
                bias = b1; cst = c1;
                Ho = h1sw + (size_t)(p % 3) * IMG;
                op = nullptr;
            } else {
                bias = b2; cst = c2;
                Ho = h2sw + (size_t)(p & 1) * IMG;
                op = (p == 256) ? out : nullptr;
            }

            float acc[4][4][4];
#pragma unroll
            for (int mi = 0; mi < 4; mi++)
#pragma unroll
                for (int nf = 0; nf < 4; nf++)
#pragma unroll
                    for (int cc = 0; cc < 4; cc++) acc[mi][nf][cc] = 0.f;

            uint32_t aF[2][4][4], bF[2][4][2];

            // prologue: wait first chunk's stage, preload k16=0 into buf 0
            unsigned g = cg;
            MBAR_WAIT(mb_full + (g % 3u) * 8, (g / 3u) & 1);
            uint32_t stgc = sb + (g % 3u) * 65536u;
            load_frags(aF[0], bF[0], stgc, 0, baseA, baseB, khalf, xr);

#pragma unroll 1
            for (int cc = 0; cc < 16; cc++) {
#pragma unroll
                for (int k16 = 0; k16 < 8; k16++) {
                    const int cb = k16 & 1, nb = cb ^ 1;
                    if (k16 < 7) {
                        load_frags(aF[nb], bF[nb], stgc, k16 + 1, baseA, baseB, khalf, xr);
                        mma_block(acc, aF[cb], bF[cb]);
                    } else {
                        mma_block(acc, aF[cb], bF[cb]);
                        MBAR_ARRIVE(mb_cons + (g % 3u) * 8);
                        if (cc < 15) {
                            const unsigned g2 = g + 1;
                            MBAR_WAIT(mb_full + (g2 % 3u) * 8, (g2 / 3u) & 1);
                            load_frags(aF[nb], bF[nb], sb + (g2 % 3u) * 65536u, 0,
                                       baseA, baseB, khalf, xr);
                        }
                    }
                }
                g++;
                stgc = sb + (g % 3u) * 65536u;
            }
            cg += 16;

            // ---------- fused gate epilogue (identical to R15) ----------
            const int q = lane & 3, gg = lane >> 2;
            const int gbase = (nt * 4 + wn) * 8;
            float bi[2][4];
#pragma unroll
            for (int ue = 0; ue < 2; ue++) {
                int u = gbase + q + 4 * ue;
                bi[ue][0] = bias[u];
                bi[ue][1] = bias[NH + u];
                bi[ue][2] = bias[2 * NH + u] + 1.0f;
                bi[ue][3] = bias[3 * NH + u];
            }

            float* cvec = cst + ((size_t)blockIdx.x * 256 + tid) * 16;
            float cva[16];
#pragma unroll
            for (int v = 0; v < 4; v++)
                *(float4*)(cva + 4 * v) = ((const float4*)cvec)[v];

#pragma unroll
            for (int mi = 0; mi < 4; mi++) {
#pragma unroll
                for (int d = 0; d < 2; d++) {
                    const int rl = wm * 64 + mi * 16 + gg + 8 * d;
                    const int rg = mt * 128 + rl;
#pragma unroll
                    for (int ue = 0; ue < 2; ue++) {
                        const int u = gbase + q + 4 * ue;
                        float zi = acc[mi][ue][2 * d + 0]     + bi[ue][0];
                        float zj = acc[mi][ue][2 * d + 1]     + bi[ue][1];
                        float zf = acc[mi][2 + ue][2 * d + 0] + bi[ue][2];
                        float zo = acc[mi][2 + ue][2 * d + 1] + bi[ue][3];

                        const int slot = mi * 4 + d * 2 + ue;
                        float cn = cva[slot] * sigf(zf) + sigf(zi) * tanhfast(zj);
                        cva[slot] = cn;
                        float hv = tanhfast(cn) * sigf(zo);

                        int kc = u >> 6, kl = u & 63;
                        size_t ib = (size_t)(mt * 16 + kc) * TILE_ELEMS;
                        uint32_t off = (uint32_t)(rl * 128) + (uint32_t)((kl * 2) ^ ((rl & 7) << 4));
                        *(__half*)((char*)(Ho + ib) + off) = __float2half_rn(hv);

                        if (op) op[(size_t)rg * NH + u] = hv;
                    }
                }
            }
#pragma unroll
            for (int v = 0; v < 4; v++)
                ((float4*)cvec)[v] = *(float4*)(cva + 4 * v);
        }

        // ---------- single per-phase epoch post (R15 semantics) ----------
        CONS_BAR();
        if (tid == 0) {
            __threadfence();
            atomicAdd(&g_barm[mt], 1u);
        }
    }
}

// ---------------------------------------------------------------------------
extern "C" void kernel_launch(void* const* d_in, const int* in_sizes, int n_in,
                              void* d_out, int out_size)
{
    const float* x  = (const float*)d_in[0];
    const float* W  = (const float*)d_in[1];
    const float* bh = (const float*)d_in[2];
    const float* k1 = (const float*)d_in[3];
    const float* b1 = (const float*)d_in[4];
    const float* k2 = (const float*)d_in[5];
    const float* b2 = (const float*)d_in[6];
    float* out = (float*)d_out;

    __half *xsw, *h1sw, *h2sw, *w1sw, *w2sw;
    float *c1, *c2;
    cudaGetSymbolAddress((void**)&xsw,  g_xsw);
    cudaGetSymbolAddress((void**)&h1sw, g_h1sw);
    cudaGetSymbolAddress((void**)&h2sw, g_h2sw);
    cudaGetSymbolAddress((void**)&w1sw, g_w1sw);
    cudaGetSymbolAddress((void**)&w2sw, g_w2sw);
    cudaGetSymbolAddress((void**)&c1,   g_c1);
    cudaGetSymbolAddress((void**)&c2,   g_c2);

    const int SMEM_BYTES = 196608 + 128;
    static bool attr_set = false;
    if (!attr_set) {
        cudaFuncSetAttribute(lstm_persistent,
                             cudaFuncAttributeMaxDynamicSharedMemorySize, SMEM_BYTES);
        cudaFuncSetAttribute(proj_hmma,
                             cudaFuncAttributeMaxDynamicSharedMemorySize, SMEM_BYTES);
        attr_set = true;
    }

    zero_kernel<<<(Bsz * NH + 255) / 256, 256>>>();
    wconv_kernel<<<4096, 256>>>(k1, w1sw);
    wconv_kernel<<<4096, 256>>>(k2, w2sw);
    wconvh_kernel<<<64, 256>>>(W);
    xconv_kernel<<<8192, 256>>>(x);
    proj_hmma<<<dim3(8, 16), 288, SMEM_BYTES>>>(bh);

    lstm_persistent<<<NCTA, 288, SMEM_BYTES>>>(
        xsw, h1sw, h2sw, w1sw, w2sw, b1, b2, c1, c2, out);
}